// round 2
// baseline (speedup 1.0000x reference)
#include <cuda_runtime.h>
#include <math.h>

#define HH 256
#define WW 320
#define CCH 28
#define HWSZ (HH*WW)          // 81920
#define NB 2
#define NELEM (NB*CCH*HWSZ)   // 4587520
#define NPIX (NB*HWSZ)        // 163840

// ---------------- scratch (static device globals; no runtime allocation) -----
__device__ float g_xn[NELEM];     // NCHW input / reused as y (hf1 out)
__device__ float g_tmp[NELEM];    // DCT pass-1 intermediate (both directions)
__device__ float g_xdct[NELEM];   // DCT of input
__device__ float g_xlow[NELEM];   // spectral attention branch out (NCHW)
__device__ float g_xconv[NELEM];  // dw-conv + residual
__device__ float g_xout[NELEM];   // combined, pre-inverse-DCT
__device__ float g_fd[NELEM];     // out_fd (NCHW)
__device__ float g_loc[NELEM];    // out_local (NCHW)
__device__ float g_DH[256*256];
__device__ float g_DW[320*320];
__device__ float g_DIH[256*256];
__device__ float g_DIW[320*320];

__device__ __forceinline__ float gelu_f(float x){
    return 0.5f*x*(1.0f + erff(x*0.7071067811865476f));
}

// ---------------- DCT matrix generation --------------------------------------
__global__ void fill_dct_fwd(float* D, int N){
    int i = blockIdx.x*blockDim.x + threadIdx.x;
    if (i < N*N){
        int k = i / N, n = i % N;
        double v = 2.0*cos(3.14159265358979323846*(2.0*n+1.0)*(double)k/(2.0*N));
        D[i] = (float)v;
    }
}
__global__ void fill_dct_inv(float* D, int N){
    int i = blockIdx.x*blockDim.x + threadIdx.x;
    if (i < N*N){
        int n = i / N, k = i % N;
        double v;
        if (k == 0) v = 1.0/(2.0*N);
        else        v = cos(3.14159265358979323846*(2.0*n+1.0)*(double)k/(2.0*N))/(double)N;
        D[i] = (float)v;
    }
}

// ---------------- NHWC -> NCHW transpose -------------------------------------
__global__ __launch_bounds__(256) void transpose_in(const float* __restrict__ x){
    __shared__ float s[32*28];
    int blk = blockIdx.x;
    int b   = blk / (HWSZ/32);
    int hw0 = (blk % (HWSZ/32)) * 32;
    const float* src = x + ((long)b*HWSZ + hw0)*CCH;
    for (int idx = threadIdx.x; idx < 32*CCH; idx += blockDim.x) s[idx] = src[idx];
    __syncthreads();
    for (int idx = threadIdx.x; idx < 32*CCH; idx += blockDim.x){
        int c = idx / 32, i = idx % 32;
        g_xn[((long)b*CCH + c)*HWSZ + hw0 + i] = s[i*CCH + c];
    }
}

// ---------------- batched tiled fp32 GEMM ------------------------------------
// TB=false : C[m,n] = sum_k A[m,k]*B[k,n]
// TB=true  : C[m,n] = sum_k A[m,k]*B[n,k]
template<bool TB>
__global__ __launch_bounds__(256) void gemm_kernel(
    const float* __restrict__ A, int lda, int sA,
    const float* __restrict__ B, int ldb, int sB,
    float* __restrict__ C, int ldc, int sC,
    int M, int N, int Kd)
{
    __shared__ float As[16][64];
    __shared__ float Bs[16][64];
    int z = blockIdx.z;
    A += (long)z*sA; B += (long)z*sB; C += (long)z*sC;
    int m0 = blockIdx.y*64, n0 = blockIdx.x*64;
    int t = threadIdx.x;
    int tx = t & 15, ty = t >> 4;
    float acc[4][4];
#pragma unroll
    for (int i=0;i<4;i++)
#pragma unroll
        for (int j=0;j<4;j++) acc[i][j] = 0.f;

    for (int k0 = 0; k0 < Kd; k0 += 16){
        {
            int r = t >> 2, cc = (t & 3) << 2;
            float4 a4 = *reinterpret_cast<const float4*>(A + (m0+r)*lda + k0 + cc);
            As[cc+0][r]=a4.x; As[cc+1][r]=a4.y; As[cc+2][r]=a4.z; As[cc+3][r]=a4.w;
        }
        if (TB){
            int r = t >> 2, cc = (t & 3) << 2;
            float4 b4 = *reinterpret_cast<const float4*>(B + (n0+r)*ldb + k0 + cc);
            Bs[cc+0][r]=b4.x; Bs[cc+1][r]=b4.y; Bs[cc+2][r]=b4.z; Bs[cc+3][r]=b4.w;
        } else {
            int r = t >> 4, cc = (t & 15) << 2;
            float4 b4 = *reinterpret_cast<const float4*>(B + (k0+r)*ldb + n0 + cc);
            *reinterpret_cast<float4*>(&Bs[r][cc]) = b4;
        }
        __syncthreads();
#pragma unroll
        for (int kk=0; kk<16; kk++){
            float4 a4 = *reinterpret_cast<float4*>(&As[kk][ty<<2]);
            float4 b4 = *reinterpret_cast<float4*>(&Bs[kk][tx<<2]);
            float av[4] = {a4.x,a4.y,a4.z,a4.w};
            float bv[4] = {b4.x,b4.y,b4.z,b4.w};
#pragma unroll
            for (int i=0;i<4;i++)
#pragma unroll
                for (int j=0;j<4;j++) acc[i][j] += av[i]*bv[j];
        }
        __syncthreads();
    }
#pragma unroll
    for (int i=0;i<4;i++){
        float4 r4 = make_float4(acc[i][0],acc[i][1],acc[i][2],acc[i][3]);
        *reinterpret_cast<float4*>(C + (m0+(ty<<2)+i)*ldc + n0 + (tx<<2)) = r4;
    }
}

// ---------------- spectral attention (per 8x8 DCT block) ---------------------
__global__ __launch_bounds__(256) void spec_attn_kernel(
    const float* __restrict__ wq, const float* __restrict__ wk,
    const float* __restrict__ wv, const float* __restrict__ rescale,
    const float* __restrict__ pw, const float* __restrict__ pb)
{
    extern __shared__ float sm[];
    float* xt   = sm;             // [64][29]  token-major
    float* qs   = xt   + 64*29;   // [28][65]  d-major
    float* ks   = qs   + 28*65;
    float* vs   = ks   + 28*65;
    float* attn = vs   + 28*65;   // [28][29]
    float* wqs  = attn + 28*29;   // [c][d] 784
    float* wks  = wqs  + 784;
    float* wvs  = wks  + 784;
    float* pws  = wvs  + 784;     // [d][c] 784
    float* oacc = pws  + 784;     // [64][29] token-major
    float* invq = oacc + 64*29;   // 28
    float* invk = invq + 28;      // 28

    int blk = blockIdx.x;
    int b = blk / 1280;
    int n = blk % 1280;
    int ph = n / 40, pwi = n % 40;
    int t = threadIdx.x;
    long base = (long)b*CCH*HWSZ + (long)ph*8*WW + pwi*8;

    for (int idx = t; idx < 1792; idx += 256){
        int c = idx >> 6, m = idx & 63;
        int i = m >> 3, j = m & 7;
        xt[m*29 + c] = g_xdct[base + (long)c*HWSZ + i*WW + j];
    }
    for (int idx = t; idx < 1792; idx += 256){
        int m = idx / 28, c = idx % 28;
        oacc[m*29 + c] = pb[c];
    }

    for (int h = 0; h < 8; h++){
        __syncthreads();
        for (int idx = t; idx < 784; idx += 256){
            int c = idx / 28, d = idx % 28;
            int col = h*28 + d;
            wqs[idx] = wq[c*224 + col];
            wks[idx] = wk[c*224 + col];
            wvs[idx] = wv[c*224 + col];
            pws[d*28 + c] = pw[col*28 + c];
        }
        __syncthreads();
        // q,k,v projections: out [d][m]
        if (t < 224){
            int d0 = (t >> 4) * 2;
            int m0 = (t & 15) * 4;
            float aq[2][4], ak[2][4], av[2][4];
#pragma unroll
            for (int i=0;i<2;i++)
#pragma unroll
                for (int j=0;j<4;j++){ aq[i][j]=0; ak[i][j]=0; av[i][j]=0; }
#pragma unroll 4
            for (int c = 0; c < 28; c++){
                float xv[4];
#pragma unroll
                for (int j=0;j<4;j++) xv[j] = xt[(m0+j)*29 + c];
                float w0q = wqs[c*28+d0], w1q = wqs[c*28+d0+1];
                float w0k = wks[c*28+d0], w1k = wks[c*28+d0+1];
                float w0v = wvs[c*28+d0], w1v = wvs[c*28+d0+1];
#pragma unroll
                for (int j=0;j<4;j++){
                    aq[0][j] += xv[j]*w0q; aq[1][j] += xv[j]*w1q;
                    ak[0][j] += xv[j]*w0k; ak[1][j] += xv[j]*w1k;
                    av[0][j] += xv[j]*w0v; av[1][j] += xv[j]*w1v;
                }
            }
#pragma unroll
            for (int i=0;i<2;i++)
#pragma unroll
                for (int j=0;j<4;j++){
                    qs[(d0+i)*65 + m0+j] = aq[i][j];
                    ks[(d0+i)*65 + m0+j] = ak[i][j];
                    vs[(d0+i)*65 + m0+j] = av[i][j];
                }
        }
        __syncthreads();
        // l2 norms along m
        if (t < 56){
            int d = t % 28;
            float* p = (t < 28) ? qs : ks;
            float s = 0.f;
#pragma unroll 8
            for (int m=0;m<64;m++){ float v = p[d*65+m]; s += v*v; }
            float inv = 1.0f / fmaxf(sqrtf(s), 1e-12f);
            if (t < 28) invq[d] = inv; else invk[d] = inv;
        }
        __syncthreads();
        // attn[d][e]
        float rs = rescale[h];
        if (t < 196){
            int d0 = (t / 14) * 2;
            int e0 = (t % 14) * 2;
            float a00=0,a01=0,a10=0,a11=0;
#pragma unroll 8
            for (int m=0;m<64;m++){
                float q0 = qs[d0*65+m], q1 = qs[(d0+1)*65+m];
                float k0 = ks[e0*65+m], k1 = ks[(e0+1)*65+m];
                a00 += q0*k0; a01 += q0*k1; a10 += q1*k0; a11 += q1*k1;
            }
            attn[d0*29 + e0]       = a00*invq[d0]  *invk[e0]  *rs;
            attn[d0*29 + e0+1]     = a01*invq[d0]  *invk[e0+1]*rs;
            attn[(d0+1)*29 + e0]   = a10*invq[d0+1]*invk[e0]  *rs;
            attn[(d0+1)*29 + e0+1] = a11*invq[d0+1]*invk[e0+1]*rs;
        }
        __syncthreads();
        // softmax over e
        if (t < 28){
            float* row = attn + t*29;
            float mx = row[0];
#pragma unroll
            for (int e=1;e<28;e++) mx = fmaxf(mx, row[e]);
            float s = 0.f;
#pragma unroll
            for (int e=0;e<28;e++){ float ev = expf(row[e]-mx); row[e]=ev; s += ev; }
            float invs = 1.0f/s;
#pragma unroll
            for (int e=0;e<28;e++) row[e] *= invs;
        }
        __syncthreads();
        // x0 = attn @ v -> overwrite qs ([d][m])
        if (t < 224){
            int d0 = (t >> 4) * 2;
            int m0 = (t & 15) * 4;
            float acc[2][4];
#pragma unroll
            for (int i=0;i<2;i++)
#pragma unroll
                for (int j=0;j<4;j++) acc[i][j]=0;
#pragma unroll 4
            for (int e=0;e<28;e++){
                float a0 = attn[d0*29+e], a1 = attn[(d0+1)*29+e];
                float vv[4];
#pragma unroll
                for (int j=0;j<4;j++) vv[j] = vs[e*65 + m0+j];
#pragma unroll
                for (int j=0;j<4;j++){ acc[0][j]+=a0*vv[j]; acc[1][j]+=a1*vv[j]; }
            }
#pragma unroll
            for (int i=0;i<2;i++)
#pragma unroll
                for (int j=0;j<4;j++) qs[(d0+i)*65 + m0+j] = acc[i][j];
        }
        __syncthreads();
        // oacc[m][c] += sum_d x0[d][m]*pw[d][c]
        if (t < 224){
            int c0 = (t >> 4) * 2;
            int m0 = (t & 15) * 4;
            float acc[4][2];
#pragma unroll
            for (int j=0;j<4;j++){ acc[j][0]=0; acc[j][1]=0; }
#pragma unroll 4
            for (int d=0;d<28;d++){
                float p0 = pws[d*28+c0], p1 = pws[d*28+c0+1];
                float xv[4];
#pragma unroll
                for (int j=0;j<4;j++) xv[j] = qs[d*65 + m0+j];
#pragma unroll
                for (int j=0;j<4;j++){ acc[j][0]+=xv[j]*p0; acc[j][1]+=xv[j]*p1; }
            }
#pragma unroll
            for (int j=0;j<4;j++){
                oacc[(m0+j)*29 + c0]   += acc[j][0];
                oacc[(m0+j)*29 + c0+1] += acc[j][1];
            }
        }
    }
    __syncthreads();
    for (int idx = t; idx < 1792; idx += 256){
        int c = idx >> 6, m = idx & 63;
        int i = m >> 3, j = m & 7;
        g_xlow[base + (long)c*HWSZ + i*WW + j] = oacc[m*29 + c];
    }
}

// ---------------- local window attention -------------------------------------
__global__ __launch_bounds__(256) void local_attn_kernel(
    const float* __restrict__ x, const float* __restrict__ wq,
    const float* __restrict__ wkv, const float* __restrict__ pos,
    const float* __restrict__ pw, const float* __restrict__ pb)
{
    extern __shared__ float sm[];
    float* xw  = sm;            // [64][29] token-major
    float* qs  = xw  + 64*29;   // [64][29] token-major (i,d)
    float* ks  = qs  + 64*29;
    float* vs  = ks  + 64*29;
    float* sim = vs  + 64*29;   // [64][65]
    float* wqs = sim + 64*65;   // [c][d]
    float* wks = wqs + 784;
    float* wvs = wks + 784;
    float* pws = wvs + 784;     // [d][c]
    float* oacc= pws + 784;     // [64][29]

    int blk = blockIdx.x;
    int b = blk / 1280;
    int n = blk % 1280;
    int ph = n / 40, pwi = n % 40;
    int t = threadIdx.x;
    long basex = (((long)b*HH + ph*8)*WW + pwi*8)*CCH;

    for (int idx = t; idx < 1792; idx += 256){
        int i = idx / 28, c = idx % 28;
        int r = i >> 3, s2 = i & 7;
        xw[i*29 + c] = x[basex + (r*WW + s2)*CCH + c];
    }
    for (int idx = t; idx < 1792; idx += 256){
        int m = idx / 28, c = idx % 28;
        oacc[m*29 + c] = pb[c];
    }
    const float qscale = 0.18898223650461363f; // 28^-0.5

    for (int h = 0; h < 8; h++){
        __syncthreads();
        for (int idx = t; idx < 784; idx += 256){
            int c = idx / 28, d = idx % 28;
            int col = h*28 + d;
            wqs[idx] = wq[c*224 + col];
            wks[idx] = wkv[c*448 + col];
            wvs[idx] = wkv[c*448 + 224 + col];
            pws[d*28 + c] = pw[col*28 + c];
        }
        __syncthreads();
        // projections -> [i][d]
        if (t < 224){
            int i0 = (t & 15) * 4;
            int d0 = (t >> 4) * 2;
            float aq[4][2], ak[4][2], av[4][2];
#pragma unroll
            for (int i=0;i<4;i++){ aq[i][0]=aq[i][1]=ak[i][0]=ak[i][1]=av[i][0]=av[i][1]=0; }
#pragma unroll 4
            for (int c=0;c<28;c++){
                float xv[4];
#pragma unroll
                for (int i=0;i<4;i++) xv[i] = xw[(i0+i)*29 + c];
                float w0q=wqs[c*28+d0], w1q=wqs[c*28+d0+1];
                float w0k=wks[c*28+d0], w1k=wks[c*28+d0+1];
                float w0v=wvs[c*28+d0], w1v=wvs[c*28+d0+1];
#pragma unroll
                for (int i=0;i<4;i++){
                    aq[i][0]+=xv[i]*w0q; aq[i][1]+=xv[i]*w1q;
                    ak[i][0]+=xv[i]*w0k; ak[i][1]+=xv[i]*w1k;
                    av[i][0]+=xv[i]*w0v; av[i][1]+=xv[i]*w1v;
                }
            }
#pragma unroll
            for (int i=0;i<4;i++){
                qs[(i0+i)*29 + d0]   = aq[i][0]*qscale;
                qs[(i0+i)*29 + d0+1] = aq[i][1]*qscale;
                ks[(i0+i)*29 + d0]   = ak[i][0];
                ks[(i0+i)*29 + d0+1] = ak[i][1];
                vs[(i0+i)*29 + d0]   = av[i][0];
                vs[(i0+i)*29 + d0+1] = av[i][1];
            }
        }
        __syncthreads();
        // sim[i][j] = q.k + pos
        {
            int i0 = (t >> 4) * 4;
            int j0 = (t & 15) * 4;
            float acc[4][4];
#pragma unroll
            for (int i=0;i<4;i++)
#pragma unroll
                for (int j=0;j<4;j++) acc[i][j]=0;
#pragma unroll 4
            for (int d=0;d<28;d++){
                float qv[4], kv[4];
#pragma unroll
                for (int i=0;i<4;i++) qv[i] = qs[(i0+i)*29 + d];
#pragma unroll
                for (int j=0;j<4;j++) kv[j] = ks[(j0+j)*29 + d];
#pragma unroll
                for (int i=0;i<4;i++)
#pragma unroll
                    for (int j=0;j<4;j++) acc[i][j] += qv[i]*kv[j];
            }
            const float* ph2 = pos + h*4096;
#pragma unroll
            for (int i=0;i<4;i++)
#pragma unroll
                for (int j=0;j<4;j++)
                    sim[(i0+i)*65 + j0+j] = acc[i][j] + ph2[(i0+i)*64 + j0+j];
        }
        __syncthreads();
        // softmax rows
        if (t < 64){
            float* row = sim + t*65;
            float mx = row[0];
#pragma unroll 8
            for (int j=1;j<64;j++) mx = fmaxf(mx, row[j]);
            float s = 0.f;
#pragma unroll 8
            for (int j=0;j<64;j++){ float ev = expf(row[j]-mx); row[j]=ev; s+=ev; }
            float invs = 1.0f/s;
#pragma unroll 8
            for (int j=0;j<64;j++) row[j] *= invs;
        }
        __syncthreads();
        // o = a @ v -> overwrite qs ([i][d])
        if (t < 224){
            int i0 = (t & 15) * 4;
            int d0 = (t >> 4) * 2;
            float acc[4][2];
#pragma unroll
            for (int i=0;i<4;i++){ acc[i][0]=0; acc[i][1]=0; }
#pragma unroll 4
            for (int j=0;j<64;j++){
                float v0 = vs[j*29 + d0], v1 = vs[j*29 + d0+1];
                float sv[4];
#pragma unroll
                for (int i=0;i<4;i++) sv[i] = sim[(i0+i)*65 + j];
#pragma unroll
                for (int i=0;i<4;i++){ acc[i][0]+=sv[i]*v0; acc[i][1]+=sv[i]*v1; }
            }
#pragma unroll
            for (int i=0;i<4;i++){
                qs[(i0+i)*29 + d0]   = acc[i][0];
                qs[(i0+i)*29 + d0+1] = acc[i][1];
            }
        }
        __syncthreads();
        // oacc[i][c] += sum_d o[i][d]*pw[d][c]
        if (t < 224){
            int i0 = (t & 15) * 4;
            int c0 = (t >> 4) * 2;
            float acc[4][2];
#pragma unroll
            for (int i=0;i<4;i++){ acc[i][0]=0; acc[i][1]=0; }
#pragma unroll 4
            for (int d=0;d<28;d++){
                float p0 = pws[d*28+c0], p1 = pws[d*28+c0+1];
                float ov[4];
#pragma unroll
                for (int i=0;i<4;i++) ov[i] = qs[(i0+i)*29 + d];
#pragma unroll
                for (int i=0;i<4;i++){ acc[i][0]+=ov[i]*p0; acc[i][1]+=ov[i]*p1; }
            }
#pragma unroll
            for (int i=0;i<4;i++){
                oacc[(i0+i)*29 + c0]   += acc[i][0];
                oacc[(i0+i)*29 + c0+1] += acc[i][1];
            }
        }
    }
    __syncthreads();
    for (int idx = t; idx < 1792; idx += 256){
        int c = idx >> 6, m = idx & 63;
        int r = m >> 3, s2 = m & 7;
        g_loc[((long)b*CCH + c)*HWSZ + (ph*8 + r)*WW + pwi*8 + s2] = oacc[m*29 + c];
    }
}

// ---------------- high-frequency conv path -----------------------------------
__global__ __launch_bounds__(256) void pw1_gelu_kernel(const float* __restrict__ W){
    __shared__ float Ws[784];
    for (int idx = threadIdx.x; idx < 784; idx += 256) Ws[idx] = W[idx];
    __syncthreads();
    int p = blockIdx.x*256 + threadIdx.x;     // pixel id over B*HW
    int b = p / HWSZ; int hw = p % HWSZ;
    long base = (long)b*CCH*HWSZ + hw;
    float xin[28];
#pragma unroll
    for (int c=0;c<28;c++) xin[c] = g_xdct[base + (long)c*HWSZ];
#pragma unroll 2
    for (int o=0;o<28;o++){
        float s = 0.f;
#pragma unroll
        for (int c=0;c<28;c++) s += Ws[o*28+c]*xin[c];
        g_xn[base + (long)o*HWSZ] = gelu_f(s);
    }
}

__global__ __launch_bounds__(256) void dw_gelu_add_kernel(const float* __restrict__ Wd){
    int id = blockIdx.x*256 + threadIdx.x;
    if (id >= NELEM) return;
    int w = id % WW;
    int r1 = id / WW;
    int h = r1 % HH;
    int bc = r1 / HH;
    int c = bc % CCH;
    float acc = 0.f;
#pragma unroll
    for (int dh=-1; dh<=1; dh++){
        int hy = h + dh;
        if (hy < 0 || hy >= HH) continue;
#pragma unroll
        for (int dw2=-1; dw2<=1; dw2++){
            int wx = w + dw2;
            if (wx < 0 || wx >= WW) continue;
            acc += g_xn[((long)bc*HH + hy)*WW + wx] * Wd[c*9 + (dh+1)*3 + (dw2+1)];
        }
    }
    g_xconv[id] = gelu_f(acc) + g_xdct[id];
}

__global__ __launch_bounds__(256) void combine_kernel(
    const float* __restrict__ W2, const float* __restrict__ coef)
{
    __shared__ float Ws[784];
    for (int idx = threadIdx.x; idx < 784; idx += 256) Ws[idx] = W2[idx];
    __syncthreads();
    int p = blockIdx.x*256 + threadIdx.x;
    int b = p / HWSZ; int hw = p % HWSZ;
    long base = (long)b*CCH*HWSZ + hw;
    float xc[28];
#pragma unroll
    for (int c=0;c<28;c++) xc[c] = g_xconv[base + (long)c*HWSZ];
    float cf = coef[hw];
#pragma unroll 2
    for (int o=0;o<28;o++){
        float s = 0.f;
#pragma unroll
        for (int c=0;c<28;c++) s += Ws[o*28+c]*xc[c];
        float th = gelu_f(s) + xc[o];
        long off = base + (long)o*HWSZ;
        g_xout[off] = cf*g_xlow[off] + (1.0f-cf)*th + g_xdct[off];
    }
}

// ---------------- fusion ------------------------------------------------------
__global__ __launch_bounds__(256) void fusion_kernel(
    const float* __restrict__ fw, const float* __restrict__ fb,
    float* __restrict__ out)
{
    __shared__ float Ws[28*56];
    __shared__ float fbs[28];
    __shared__ float so[256*28];
    for (int idx = threadIdx.x; idx < 28*56; idx += 256) Ws[idx] = fw[idx];
    if (threadIdx.x < 28) fbs[threadIdx.x] = fb[threadIdx.x];
    __syncthreads();
    int p = blockIdx.x*256 + threadIdx.x;
    int b = p / HWSZ; int hw = p % HWSZ;
    long base = (long)b*CCH*HWSZ + hw;
    float fd[28], lc[28];
#pragma unroll
    for (int c=0;c<28;c++){
        fd[c] = g_fd[base + (long)c*HWSZ];
        lc[c] = g_loc[base + (long)c*HWSZ];
    }
#pragma unroll 2
    for (int o=0;o<28;o++){
        float s = fbs[o];
#pragma unroll
        for (int c=0;c<28;c++) s += Ws[o*56 + c]*fd[c] + Ws[o*56 + 28 + c]*lc[c];
        so[threadIdx.x*28 + o] = s;
    }
    __syncthreads();
    long obase = (long)blockIdx.x*256*28;
    for (int idx = threadIdx.x; idx < 256*28; idx += 256) out[obase + idx] = so[idx];
}

// ---------------- launch ------------------------------------------------------
extern "C" void kernel_launch(void* const* d_in, const int* in_sizes, int n_in,
                              void* d_out, int out_size)
{
    const float* x          = (const float*)d_in[0];
    const float* spec_wq    = (const float*)d_in[1];
    const float* spec_wk    = (const float*)d_in[2];
    const float* spec_wv    = (const float*)d_in[3];
    const float* spec_rs    = (const float*)d_in[4];
    const float* spec_pw    = (const float*)d_in[5];
    const float* spec_pb    = (const float*)d_in[6];
    const float* hf1_pw_w   = (const float*)d_in[7];
    const float* hf1_dw_w   = (const float*)d_in[8];
    const float* hf2_pw_w   = (const float*)d_in[9];
    const float* coef_emb   = (const float*)d_in[10];
    const float* loc_wq     = (const float*)d_in[11];
    const float* loc_wkv    = (const float*)d_in[12];
    const float* loc_pos    = (const float*)d_in[13];
    const float* loc_pw     = (const float*)d_in[14];
    const float* loc_pb     = (const float*)d_in[15];
    const float* fus_w      = (const float*)d_in[16];
    const float* fus_b      = (const float*)d_in[17];
    float* out = (float*)d_out;

    float *p_xn, *p_tmp, *p_xdct, *p_xout, *p_fd;
    float *p_DH, *p_DW, *p_DIH, *p_DIW;
    cudaGetSymbolAddress((void**)&p_xn,   g_xn);
    cudaGetSymbolAddress((void**)&p_tmp,  g_tmp);
    cudaGetSymbolAddress((void**)&p_xdct, g_xdct);
    cudaGetSymbolAddress((void**)&p_xout, g_xout);
    cudaGetSymbolAddress((void**)&p_fd,   g_fd);
    cudaGetSymbolAddress((void**)&p_DH,   g_DH);
    cudaGetSymbolAddress((void**)&p_DW,   g_DW);
    cudaGetSymbolAddress((void**)&p_DIH,  g_DIH);
    cudaGetSymbolAddress((void**)&p_DIW,  g_DIW);

    const int SPEC_SMEM  = 13176 * 4;   // 52704 B
    const int LOCAL_SMEM = 16576 * 4;   // 66304 B
    cudaFuncSetAttribute(spec_attn_kernel,  cudaFuncAttributeMaxDynamicSharedMemorySize, SPEC_SMEM);
    cudaFuncSetAttribute(local_attn_kernel, cudaFuncAttributeMaxDynamicSharedMemorySize, LOCAL_SMEM);

    // DCT matrices
    fill_dct_fwd<<<(256*256+255)/256, 256>>>(p_DH, 256);
    fill_dct_fwd<<<(320*320+255)/256, 256>>>(p_DW, 320);
    fill_dct_inv<<<(256*256+255)/256, 256>>>(p_DIH, 256);
    fill_dct_inv<<<(320*320+255)/256, 256>>>(p_DIW, 320);

    // NHWC -> NCHW
    transpose_in<<<NB*(HWSZ/32), 256>>>(x);

    // forward 2D DCT: tmp = D_H * xn ; xdct = tmp * D_W^T   (batched over b*c=56)
    gemm_kernel<false><<<dim3(5,4,56), 256>>>(p_DH, 256, 0,  p_xn, 320, HWSZ,
                                              p_tmp, 320, HWSZ, 256, 320, 256);
    gemm_kernel<true ><<<dim3(5,4,56), 256>>>(p_tmp, 320, HWSZ, p_DW, 320, 0,
                                              p_xdct, 320, HWSZ, 256, 320, 320);

    // spectral attention branch -> g_xlow
    spec_attn_kernel<<<2560, 256, SPEC_SMEM>>>(spec_wq, spec_wk, spec_wv,
                                               spec_rs, spec_pw, spec_pb);

    // high-frequency path
    pw1_gelu_kernel<<<NPIX/256, 256>>>(hf1_pw_w);
    dw_gelu_add_kernel<<<(NELEM+255)/256, 256>>>(hf1_dw_w);
    combine_kernel<<<NPIX/256, 256>>>(hf2_pw_w, coef_emb);

    // inverse 2D DCT: tmp = DI_H * xout ; fd = tmp * DI_W^T
    gemm_kernel<false><<<dim3(5,4,56), 256>>>(p_DIH, 256, 0, p_xout, 320, HWSZ,
                                              p_tmp, 320, HWSZ, 256, 320, 256);
    gemm_kernel<true ><<<dim3(5,4,56), 256>>>(p_tmp, 320, HWSZ, p_DIW, 320, 0,
                                              p_fd, 320, HWSZ, 256, 320, 320);

    // local attention branch -> g_loc
    local_attn_kernel<<<2560, 256, LOCAL_SMEM>>>(x, loc_wq, loc_wkv, loc_pos,
                                                 loc_pw, loc_pb);

    // fusion -> NHWC output
    fusion_kernel<<<NPIX/256, 256>>>(fus_w, fus_b, out);
}

// round 5
// speedup vs baseline: 1.1157x; 1.1157x over previous
#include <cuda_runtime.h>
#include <math.h>

#define HH 256
#define WW 320
#define CCH 28
#define HWSZ (HH*WW)          // 81920
#define NB 2
#define NELEM (NB*CCH*HWSZ)   // 4587520
#define NPIX (NB*HWSZ)        // 163840

// ---------------- scratch (static device globals; no runtime allocation) -----
__device__ float g_xn[NELEM];     // NCHW input / reused as y (hf1 out)
__device__ float g_tmp[NELEM];    // DCT pass-1 intermediate (both directions)
__device__ float g_xdct[NELEM];   // DCT of input
__device__ float g_xlow[NELEM];   // spectral attention branch out (NCHW)
__device__ float g_xconv[NELEM];  // dw-conv + residual
__device__ float g_xout[NELEM];   // combined, pre-inverse-DCT
__device__ float g_fd[NELEM];     // out_fd (NCHW)
__device__ float g_loc[NELEM];    // out_local (NCHW)
__device__ float g_DH[256*256];
__device__ float g_DW[320*320];
__device__ float g_DIH[256*256];
__device__ float g_DIW[320*320];
__device__ float g_gqk[8*784];    // fused local-attn  s * Wq Wk^T  per head
__device__ float g_wvp[8*784];    // fused local-attn  Wv @ P       per head

__device__ __forceinline__ float gelu_f(float x){
    return 0.5f*x*(1.0f + erff(x*0.7071067811865476f));
}

// ---------------- DCT matrix generation (exact int reduction + cospif) -------
__global__ void fill_dct_fwd(float* D, int N){
    int i = blockIdx.x*blockDim.x + threadIdx.x;
    if (i < N*N){
        int k = i / N, n = i % N;
        int r = ((2*n+1)*k) % (4*N);
        D[i] = 2.0f * cospif((float)r / (float)(2*N));
    }
}
__global__ void fill_dct_inv(float* D, int N){
    int i = blockIdx.x*blockDim.x + threadIdx.x;
    if (i < N*N){
        int n = i / N, k = i % N;
        if (k == 0) D[i] = 1.0f / (float)(2*N);
        else {
            int r = ((2*n+1)*k) % (4*N);
            D[i] = cospif((float)r / (float)(2*N)) / (float)N;
        }
    }
}

// ---------------- NHWC -> NCHW transpose -------------------------------------
__global__ __launch_bounds__(256) void transpose_in(const float* __restrict__ x){
    __shared__ float s[32*28];
    int blk = blockIdx.x;
    int b   = blk / (HWSZ/32);
    int hw0 = (blk % (HWSZ/32)) * 32;
    const float* src = x + ((long)b*HWSZ + hw0)*CCH;
    for (int idx = threadIdx.x; idx < 32*CCH; idx += blockDim.x) s[idx] = src[idx];
    __syncthreads();
    for (int idx = threadIdx.x; idx < 32*CCH; idx += blockDim.x){
        int c = idx / 32, i = idx % 32;
        g_xn[((long)b*CCH + c)*HWSZ + hw0 + i] = s[i*CCH + c];
    }
}

// ---------------- batched tiled fp32 GEMM ------------------------------------
template<bool TB>
__global__ __launch_bounds__(256) void gemm_kernel(
    const float* __restrict__ A, int lda, int sA,
    const float* __restrict__ B, int ldb, int sB,
    float* __restrict__ C, int ldc, int sC,
    int M, int N, int Kd)
{
    __shared__ float As[16][64];
    __shared__ float Bs[16][64];
    int z = blockIdx.z;
    A += (long)z*sA; B += (long)z*sB; C += (long)z*sC;
    int m0 = blockIdx.y*64, n0 = blockIdx.x*64;
    int t = threadIdx.x;
    int tx = t & 15, ty = t >> 4;
    float acc[4][4];
#pragma unroll
    for (int i=0;i<4;i++)
#pragma unroll
        for (int j=0;j<4;j++) acc[i][j] = 0.f;

    for (int k0 = 0; k0 < Kd; k0 += 16){
        {
            int r = t >> 2, cc = (t & 3) << 2;
            float4 a4 = *reinterpret_cast<const float4*>(A + (m0+r)*lda + k0 + cc);
            As[cc+0][r]=a4.x; As[cc+1][r]=a4.y; As[cc+2][r]=a4.z; As[cc+3][r]=a4.w;
        }
        if (TB){
            int r = t >> 2, cc = (t & 3) << 2;
            float4 b4 = *reinterpret_cast<const float4*>(B + (n0+r)*ldb + k0 + cc);
            Bs[cc+0][r]=b4.x; Bs[cc+1][r]=b4.y; Bs[cc+2][r]=b4.z; Bs[cc+3][r]=b4.w;
        } else {
            int r = t >> 4, cc = (t & 15) << 2;
            float4 b4 = *reinterpret_cast<const float4*>(B + (k0+r)*ldb + n0 + cc);
            *reinterpret_cast<float4*>(&Bs[r][cc]) = b4;
        }
        __syncthreads();
#pragma unroll
        for (int kk=0; kk<16; kk++){
            float4 a4 = *reinterpret_cast<float4*>(&As[kk][ty<<2]);
            float4 b4 = *reinterpret_cast<float4*>(&Bs[kk][tx<<2]);
            float av[4] = {a4.x,a4.y,a4.z,a4.w};
            float bv[4] = {b4.x,b4.y,b4.z,b4.w};
#pragma unroll
            for (int i=0;i<4;i++)
#pragma unroll
                for (int j=0;j<4;j++) acc[i][j] += av[i]*bv[j];
        }
        __syncthreads();
    }
#pragma unroll
    for (int i=0;i<4;i++){
        float4 r4 = make_float4(acc[i][0],acc[i][1],acc[i][2],acc[i][3]);
        *reinterpret_cast<float4*>(C + (m0+(ty<<2)+i)*ldc + n0 + (tx<<2)) = r4;
    }
}

// ---------------- spectral attention -----------------------------------------
// Logits: DIRECT per-head q,k projection (accurate: no gram cancellation).
// Value path collapsed: U_h = A_h^T P_h;  Macc += Wv_h U_h;  out = X Macc + pb.
__global__ __launch_bounds__(256) void spec_attn_kernel(
    const float* __restrict__ wq, const float* __restrict__ wk,
    const float* __restrict__ wv, const float* __restrict__ rescale,
    const float* __restrict__ pw, const float* __restrict__ pb)
{
    __shared__ float X[64*29];            // [m][c]
    __shared__ float qs[28*65], ks[28*65];// [d][m]
    __shared__ float attn[28*29];         // [d][e]
    __shared__ float wqs[784], wks[784], wvs[784], pws[784];
    __shared__ float U[784], Macc[784];
    __shared__ float invq[28], invk[28];

    int blk = blockIdx.x;
    int b = blk / 1280;
    int n = blk % 1280;
    int ph = n / 40, pwi = n % 40;
    int t = threadIdx.x;
    long base = (long)b*CCH*HWSZ + (long)ph*8*WW + pwi*8;

    for (int idx = t; idx < 1792; idx += 256){
        int c = idx >> 6, m = idx & 63;
        X[m*29 + c] = g_xdct[base + (long)c*HWSZ + (m>>3)*WW + (m&7)];
    }
    for (int idx = t; idx < 784; idx += 256) Macc[idx] = 0.f;

    for (int h = 0; h < 8; h++){
        __syncthreads();
        for (int idx = t; idx < 784; idx += 256){
            int c = idx / 28, d = idx % 28;
            int col = h*28 + d;
            wqs[idx] = wq[c*224 + col];
            wks[idx] = wk[c*224 + col];
            wvs[idx] = wv[c*224 + col];   // wvs[c][e]
            pws[d*28 + c] = pw[col*28 + c];  // pws[d][c'] = P[h*28+d, c']  (FIXED transpose)
        }
        __syncthreads();
        // q,k projections: out [d][m]
        if (t < 224){
            int d0 = (t >> 4) * 2;
            int m0 = (t & 15) * 4;
            float aq[2][4], ak[2][4];
#pragma unroll
            for (int i=0;i<2;i++)
#pragma unroll
                for (int j=0;j<4;j++){ aq[i][j]=0.f; ak[i][j]=0.f; }
#pragma unroll 4
            for (int c = 0; c < 28; c++){
                float xv[4];
#pragma unroll
                for (int j=0;j<4;j++) xv[j] = X[(m0+j)*29 + c];
                float w0q = wqs[c*28+d0], w1q = wqs[c*28+d0+1];
                float w0k = wks[c*28+d0], w1k = wks[c*28+d0+1];
#pragma unroll
                for (int j=0;j<4;j++){
                    aq[0][j] += xv[j]*w0q; aq[1][j] += xv[j]*w1q;
                    ak[0][j] += xv[j]*w0k; ak[1][j] += xv[j]*w1k;
                }
            }
#pragma unroll
            for (int i=0;i<2;i++)
#pragma unroll
                for (int j=0;j<4;j++){
                    qs[(d0+i)*65 + m0+j] = aq[i][j];
                    ks[(d0+i)*65 + m0+j] = ak[i][j];
                }
        }
        __syncthreads();
        // l2 norms along m
        if (t < 56){
            int d = t % 28;
            float* p = (t < 28) ? qs : ks;
            float s = 0.f;
#pragma unroll 8
            for (int m=0;m<64;m++){ float v = p[d*65+m]; s += v*v; }
            float inv = 1.0f / fmaxf(sqrtf(s), 1e-12f);
            if (t < 28) invq[d] = inv; else invk[d] = inv;
        }
        __syncthreads();
        // attn[d][e]
        float rs = rescale[h];
        if (t < 196){
            int d0 = (t / 14) * 2;
            int e0 = (t % 14) * 2;
            float a00=0,a01=0,a10=0,a11=0;
#pragma unroll 8
            for (int m=0;m<64;m++){
                float q0 = qs[d0*65+m], q1 = qs[(d0+1)*65+m];
                float k0 = ks[e0*65+m], k1 = ks[(e0+1)*65+m];
                a00 += q0*k0; a01 += q0*k1; a10 += q1*k0; a11 += q1*k1;
            }
            attn[d0*29 + e0]       = a00*invq[d0]  *invk[e0]  *rs;
            attn[d0*29 + e0+1]     = a01*invq[d0]  *invk[e0+1]*rs;
            attn[(d0+1)*29 + e0]   = a10*invq[d0+1]*invk[e0]  *rs;
            attn[(d0+1)*29 + e0+1] = a11*invq[d0+1]*invk[e0+1]*rs;
        }
        __syncthreads();
        // softmax over e
        if (t < 28){
            float* row = attn + t*29;
            float mx = row[0];
#pragma unroll
            for (int e=1;e<28;e++) mx = fmaxf(mx, row[e]);
            float s = 0.f;
#pragma unroll
            for (int e=0;e<28;e++){ float ev = expf(row[e]-mx); row[e]=ev; s += ev; }
            float invs = 1.0f/s;
#pragma unroll
            for (int e=0;e<28;e++) row[e] *= invs;
        }
        __syncthreads();
        // U[e][c'] = sum_d A[d][e] * pws[d][c']
        for (int idx = t; idx < 784; idx += 256){
            int e = idx / 28, cp = idx % 28;
            float s = 0.f;
#pragma unroll
            for (int d = 0; d < 28; d++) s += attn[d*29+e]*pws[d*28+cp];
            U[idx] = s;
        }
        __syncthreads();
        // Macc[c][c'] += sum_e wvs[c][e]*U[e][c']
        for (int idx = t; idx < 784; idx += 256){
            int c = idx / 28, cp = idx % 28;
            float s = 0.f;
#pragma unroll
            for (int e = 0; e < 28; e++) s += wvs[c*28+e]*U[e*28+cp];
            Macc[idx] += s;
        }
    }
    __syncthreads();
    // out = X @ Macc + pb  -> g_xlow
    for (int idx = t; idx < 1792; idx += 256){
        int m = idx / 28, cp = idx % 28;
        float s = pb[cp];
#pragma unroll
        for (int c = 0; c < 28; c++) s += X[m*29+c]*Macc[c*28+cp];
        g_xlow[base + (long)cp*HWSZ + (m>>3)*WW + (m&7)] = s;
    }
}

// ---------------- local attention fused-weight precompute --------------------
__global__ void loc_fuse_kernel(const float* __restrict__ wq,
                                const float* __restrict__ wkv,
                                const float* __restrict__ pw)
{
    int idx = blockIdx.x*blockDim.x + threadIdx.x;
    const float qscale = 0.18898223650461363f; // 28^-0.5
    if (idx < 6272){
        int h = idx / 784, r = idx % 784;
        int c = r / 28, c2 = r % 28;
        float s = 0.f;
#pragma unroll
        for (int d = 0; d < 28; d++)
            s += wq[c*224 + h*28 + d] * wkv[c2*448 + h*28 + d];
        g_gqk[idx] = s * qscale;
    } else if (idx < 12544){
        int i2 = idx - 6272;
        int h = i2 / 784, r = i2 % 784;
        int c = r / 28, cp = r % 28;
        float s = 0.f;
#pragma unroll
        for (int d = 0; d < 28; d++)
            s += wkv[c*448 + 224 + h*28 + d] * pw[(h*28 + d)*28 + cp];
        g_wvp[i2] = s;
    }
}

// ---------------- windowed local attention (fused weights) -------------------
__global__ __launch_bounds__(256) void local_attn_kernel(
    const float* __restrict__ x, const float* __restrict__ pos,
    const float* __restrict__ pb)
{
    extern __shared__ float sm[];
    float* X   = sm;            // [64][29]
    float* T   = X   + 64*29;   // [64][29]  X @ gqk_h
    float* V2  = T   + 64*29;   // [64][29]  X @ wvp_h
    float* sim = V2  + 64*29;   // [64][65]
    float* oacc= sim + 64*65;   // [64][29]
    float* wg  = oacc+ 64*29;   // 784
    float* wv2 = wg  + 784;     // 784

    int blk = blockIdx.x;
    int b = blk / 1280;
    int n = blk % 1280;
    int ph = n / 40, pwi = n % 40;
    int t = threadIdx.x;
    long basex = (((long)b*HH + ph*8)*WW + pwi*8)*CCH;

    for (int idx = t; idx < 1792; idx += 256){
        int i = idx / 28, c = idx % 28;
        X[i*29 + c] = x[basex + ((i>>3)*WW + (i&7))*CCH + c];
    }
    for (int idx = t; idx < 1792; idx += 256){
        int m = idx / 28, c = idx % 28;
        oacc[m*29 + c] = pb[c];
    }

    for (int h = 0; h < 8; h++){
        __syncthreads();
        for (int idx = t; idx < 784; idx += 256){
            wg[idx]  = g_gqk[h*784 + idx];
            wv2[idx] = g_wvp[h*784 + idx];
        }
        __syncthreads();
        // T = X@wg, V2 = X@wv2
        if (t < 224){
            int i0 = (t & 15) * 4;
            int d0 = (t >> 4) * 2;
            float aT[4][2], aV[4][2];
#pragma unroll
            for (int i=0;i<4;i++){ aT[i][0]=aT[i][1]=aV[i][0]=aV[i][1]=0.f; }
#pragma unroll 4
            for (int c=0;c<28;c++){
                float xv[4];
#pragma unroll
                for (int i=0;i<4;i++) xv[i] = X[(i0+i)*29 + c];
                float g0 = wg[c*28+d0],  g1 = wg[c*28+d0+1];
                float v0 = wv2[c*28+d0], v1 = wv2[c*28+d0+1];
#pragma unroll
                for (int i=0;i<4;i++){
                    aT[i][0]+=xv[i]*g0; aT[i][1]+=xv[i]*g1;
                    aV[i][0]+=xv[i]*v0; aV[i][1]+=xv[i]*v1;
                }
            }
#pragma unroll
            for (int i=0;i<4;i++){
                T [(i0+i)*29 + d0]   = aT[i][0];
                T [(i0+i)*29 + d0+1] = aT[i][1];
                V2[(i0+i)*29 + d0]   = aV[i][0];
                V2[(i0+i)*29 + d0+1] = aV[i][1];
            }
        }
        __syncthreads();
        // sim[i][j] = T[i][:] . X[j][:] + pos
        {
            int i0 = (t >> 4) * 4;
            int j0 = (t & 15) * 4;
            float acc[4][4];
#pragma unroll
            for (int i=0;i<4;i++)
#pragma unroll
                for (int j=0;j<4;j++) acc[i][j]=0.f;
#pragma unroll 4
            for (int d=0;d<28;d++){
                float qv[4], kv[4];
#pragma unroll
                for (int i=0;i<4;i++) qv[i] = T[(i0+i)*29 + d];
#pragma unroll
                for (int j=0;j<4;j++) kv[j] = X[(j0+j)*29 + d];
#pragma unroll
                for (int i=0;i<4;i++)
#pragma unroll
                    for (int j=0;j<4;j++) acc[i][j] += qv[i]*kv[j];
            }
            const float* ph2 = pos + h*4096;
#pragma unroll
            for (int i=0;i<4;i++)
#pragma unroll
                for (int j=0;j<4;j++)
                    sim[(i0+i)*65 + j0+j] = acc[i][j] + ph2[(i0+i)*64 + j0+j];
        }
        __syncthreads();
        // softmax rows
        if (t < 64){
            float* row = sim + t*65;
            float mx = row[0];
#pragma unroll 8
            for (int j=1;j<64;j++) mx = fmaxf(mx, row[j]);
            float s = 0.f;
#pragma unroll 8
            for (int j=0;j<64;j++){ float ev = expf(row[j]-mx); row[j]=ev; s+=ev; }
            float invs = 1.0f/s;
#pragma unroll 8
            for (int j=0;j<64;j++) row[j] *= invs;
        }
        __syncthreads();
        // oacc[i][c] += sum_j A[i][j] * V2[j][c]
        if (t < 224){
            int i0 = (t & 15) * 4;
            int c0 = (t >> 4) * 2;
            float acc[4][2];
#pragma unroll
            for (int i=0;i<4;i++){ acc[i][0]=0.f; acc[i][1]=0.f; }
#pragma unroll 4
            for (int j=0;j<64;j++){
                float v0 = V2[j*29 + c0], v1 = V2[j*29 + c0+1];
                float sv[4];
#pragma unroll
                for (int i=0;i<4;i++) sv[i] = sim[(i0+i)*65 + j];
#pragma unroll
                for (int i=0;i<4;i++){ acc[i][0]+=sv[i]*v0; acc[i][1]+=sv[i]*v1; }
            }
#pragma unroll
            for (int i=0;i<4;i++){
                oacc[(i0+i)*29 + c0]   += acc[i][0];
                oacc[(i0+i)*29 + c0+1] += acc[i][1];
            }
        }
    }
    __syncthreads();
    for (int idx = t; idx < 1792; idx += 256){
        int c = idx >> 6, m = idx & 63;
        g_loc[((long)b*CCH + c)*HWSZ + (ph*8 + (m>>3))*WW + pwi*8 + (m&7)] = oacc[m*29 + c];
    }
}

// ---------------- high-frequency conv path -----------------------------------
__global__ __launch_bounds__(256) void pw1_gelu_kernel(const float* __restrict__ W){
    __shared__ float Ws[784];
    for (int idx = threadIdx.x; idx < 784; idx += 256) Ws[idx] = W[idx];
    __syncthreads();
    int p = blockIdx.x*256 + threadIdx.x;
    int b = p / HWSZ; int hw = p % HWSZ;
    long base = (long)b*CCH*HWSZ + hw;
    float xin[28];
#pragma unroll
    for (int c=0;c<28;c++) xin[c] = g_xdct[base + (long)c*HWSZ];
#pragma unroll 2
    for (int o=0;o<28;o++){
        float s = 0.f;
#pragma unroll
        for (int c=0;c<28;c++) s += Ws[o*28+c]*xin[c];
        g_xn[base + (long)o*HWSZ] = gelu_f(s);
    }
}

__global__ __launch_bounds__(256) void dw_gelu_add_kernel(const float* __restrict__ Wd){
    int id = blockIdx.x*256 + threadIdx.x;
    if (id >= NELEM) return;
    int w = id % WW;
    int r1 = id / WW;
    int h = r1 % HH;
    int bc = r1 / HH;
    int c = bc % CCH;
    float acc = 0.f;
#pragma unroll
    for (int dh=-1; dh<=1; dh++){
        int hy = h + dh;
        if (hy < 0 || hy >= HH) continue;
#pragma unroll
        for (int dw2=-1; dw2<=1; dw2++){
            int wx = w + dw2;
            if (wx < 0 || wx >= WW) continue;
            acc += g_xn[((long)bc*HH + hy)*WW + wx] * Wd[c*9 + (dh+1)*3 + (dw2+1)];
        }
    }
    g_xconv[id] = gelu_f(acc) + g_xdct[id];
}

__global__ __launch_bounds__(256) void combine_kernel(
    const float* __restrict__ W2, const float* __restrict__ coef)
{
    __shared__ float Ws[784];
    for (int idx = threadIdx.x; idx < 784; idx += 256) Ws[idx] = W2[idx];
    __syncthreads();
    int p = blockIdx.x*256 + threadIdx.x;
    int b = p / HWSZ; int hw = p % HWSZ;
    long base = (long)b*CCH*HWSZ + hw;
    float xc[28];
#pragma unroll
    for (int c=0;c<28;c++) xc[c] = g_xconv[base + (long)c*HWSZ];
    float cf = coef[hw];
#pragma unroll 2
    for (int o=0;o<28;o++){
        float s = 0.f;
#pragma unroll
        for (int c=0;c<28;c++) s += Ws[o*28+c]*xc[c];
        float th = gelu_f(s) + xc[o];
        long off = base + (long)o*HWSZ;
        g_xout[off] = cf*g_xlow[off] + (1.0f-cf)*th + g_xdct[off];
    }
}

// ---------------- fusion ------------------------------------------------------
__global__ __launch_bounds__(256) void fusion_kernel(
    const float* __restrict__ fw, const float* __restrict__ fb,
    float* __restrict__ out)
{
    __shared__ float Ws[28*56];
    __shared__ float fbs[28];
    __shared__ float so[256*28];
    for (int idx = threadIdx.x; idx < 28*56; idx += 256) Ws[idx] = fw[idx];
    if (threadIdx.x < 28) fbs[threadIdx.x] = fb[threadIdx.x];
    __syncthreads();
    int p = blockIdx.x*256 + threadIdx.x;
    int b = p / HWSZ; int hw = p % HWSZ;
    long base = (long)b*CCH*HWSZ + hw;
    float fd[28], lc[28];
#pragma unroll
    for (int c=0;c<28;c++){
        fd[c] = g_fd[base + (long)c*HWSZ];
        lc[c] = g_loc[base + (long)c*HWSZ];
    }
#pragma unroll 2
    for (int o=0;o<28;o++){
        float s = fbs[o];
#pragma unroll
        for (int c=0;c<28;c++) s += Ws[o*56 + c]*fd[c] + Ws[o*56 + 28 + c]*lc[c];
        so[threadIdx.x*28 + o] = s;
    }
    __syncthreads();
    long obase = (long)blockIdx.x*256*28;
    for (int idx = threadIdx.x; idx < 256*28; idx += 256) out[obase + idx] = so[idx];
}

// ---------------- launch ------------------------------------------------------
extern "C" void kernel_launch(void* const* d_in, const int* in_sizes, int n_in,
                              void* d_out, int out_size)
{
    const float* x          = (const float*)d_in[0];
    const float* spec_wq    = (const float*)d_in[1];
    const float* spec_wk    = (const float*)d_in[2];
    const float* spec_wv    = (const float*)d_in[3];
    const float* spec_rs    = (const float*)d_in[4];
    const float* spec_pw    = (const float*)d_in[5];
    const float* spec_pb    = (const float*)d_in[6];
    const float* hf1_pw_w   = (const float*)d_in[7];
    const float* hf1_dw_w   = (const float*)d_in[8];
    const float* hf2_pw_w   = (const float*)d_in[9];
    const float* coef_emb   = (const float*)d_in[10];
    const float* loc_wq     = (const float*)d_in[11];
    const float* loc_wkv    = (const float*)d_in[12];
    const float* loc_pos    = (const float*)d_in[13];
    const float* loc_pw     = (const float*)d_in[14];
    const float* loc_pb     = (const float*)d_in[15];
    const float* fus_w      = (const float*)d_in[16];
    const float* fus_b      = (const float*)d_in[17];
    float* out = (float*)d_out;

    float *p_xn, *p_tmp, *p_xdct, *p_xout, *p_fd;
    float *p_DH, *p_DW, *p_DIH, *p_DIW;
    cudaGetSymbolAddress((void**)&p_xn,   g_xn);
    cudaGetSymbolAddress((void**)&p_tmp,  g_tmp);
    cudaGetSymbolAddress((void**)&p_xdct, g_xdct);
    cudaGetSymbolAddress((void**)&p_xout, g_xout);
    cudaGetSymbolAddress((void**)&p_fd,   g_fd);
    cudaGetSymbolAddress((void**)&p_DH,   g_DH);
    cudaGetSymbolAddress((void**)&p_DW,   g_DW);
    cudaGetSymbolAddress((void**)&p_DIH,  g_DIH);
    cudaGetSymbolAddress((void**)&p_DIW,  g_DIW);

    const int LOCAL_SMEM = 13152 * 4;   // 52608 B
    cudaFuncSetAttribute(local_attn_kernel, cudaFuncAttributeMaxDynamicSharedMemorySize, LOCAL_SMEM);

    // DCT matrices
    fill_dct_fwd<<<(256*256+255)/256, 256>>>(p_DH, 256);
    fill_dct_fwd<<<(320*320+255)/256, 256>>>(p_DW, 320);
    fill_dct_inv<<<(256*256+255)/256, 256>>>(p_DIH, 256);
    fill_dct_inv<<<(320*320+255)/256, 256>>>(p_DIW, 320);

    // NHWC -> NCHW
    transpose_in<<<NB*(HWSZ/32), 256>>>(x);

    // forward 2D DCT: tmp = D_H * xn ; xdct = tmp * D_W^T   (batched over b*c=56)
    gemm_kernel<false><<<dim3(5,4,56), 256>>>(p_DH, 256, 0,  p_xn, 320, HWSZ,
                                              p_tmp, 320, HWSZ, 256, 320, 256);
    gemm_kernel<true ><<<dim3(5,4,56), 256>>>(p_tmp, 320, HWSZ, p_DW, 320, 0,
                                              p_xdct, 320, HWSZ, 256, 320, 320);

    // spectral attention branch -> g_xlow
    spec_attn_kernel<<<2560, 256>>>(spec_wq, spec_wk, spec_wv,
                                    spec_rs, spec_pw, spec_pb);

    // high-frequency path
    pw1_gelu_kernel<<<NPIX/256, 256>>>(hf1_pw_w);
    dw_gelu_add_kernel<<<(NELEM+255)/256, 256>>>(hf1_dw_w);
    combine_kernel<<<NPIX/256, 256>>>(hf2_pw_w, coef_emb);

    // inverse 2D DCT: tmp = DI_H * xout ; fd = tmp * DI_W^T
    gemm_kernel<false><<<dim3(5,4,56), 256>>>(p_DIH, 256, 0, p_xout, 320, HWSZ,
                                              p_tmp, 320, HWSZ, 256, 320, 256);
    gemm_kernel<true ><<<dim3(5,4,56), 256>>>(p_tmp, 320, HWSZ, p_DIW, 320, 0,
                                              p_fd, 320, HWSZ, 256, 320, 320);

    // local attention branch -> g_loc (fused weights precomputed)
    loc_fuse_kernel<<<(12544+255)/256, 256>>>(loc_wq, loc_wkv, loc_pw);
    local_attn_kernel<<<2560, 256, LOCAL_SMEM>>>(x, loc_pos, loc_pb);

    // fusion -> NHWC output
    fusion_kernel<<<NPIX/256, 256>>>(fus_w, fus_b, out);
}

// round 6
// speedup vs baseline: 1.1331x; 1.0157x over previous
#include <cuda_runtime.h>
#include <cuda_bf16.h>
#include <mma.h>
#include <math.h>

using namespace nvcuda;

#define HH 256
#define WW 320
#define CCH 28
#define HWSZ (HH*WW)          // 81920
#define NB 2
#define NELEM (NB*CCH*HWSZ)   // 4587520
#define NPIX (NB*HWSZ)        // 163840

// ---------------- scratch (static device globals; no runtime allocation) -----
__device__ float g_xn[NELEM];     // NCHW input / reused as y (hf1 out)
__device__ float g_tmp[NELEM];    // DCT pass-1 intermediate (both directions)
__device__ float g_xdct[NELEM];   // DCT of input
__device__ float g_xlow[NELEM];   // spectral attention branch out (NCHW)
__device__ float g_xconv[NELEM];  // dw-conv + residual
__device__ float g_xout[NELEM];   // combined, pre-inverse-DCT
__device__ float g_fd[NELEM];     // out_fd (NCHW)
__device__ float g_loc[NELEM];    // out_local (NCHW)
__device__ float g_DH[256*256];
__device__ float g_DW[320*320];
__device__ float g_DIH[256*256];
__device__ float g_DIW[320*320];
__device__ float g_gqk[8*784];    // fused local-attn  s * Wq Wk^T  per head
__device__ float g_wvp[8*784];    // fused local-attn  Wv @ P       per head

__device__ __forceinline__ float gelu_f(float x){
    return 0.5f*x*(1.0f + erff(x*0.7071067811865476f));
}

// ---------------- DCT matrix generation (exact int reduction + cospif) -------
__global__ void fill_dct_fwd(float* D, int N){
    int i = blockIdx.x*blockDim.x + threadIdx.x;
    if (i < N*N){
        int k = i / N, n = i % N;
        int r = ((2*n+1)*k) % (4*N);
        D[i] = 2.0f * cospif((float)r / (float)(2*N));
    }
}
__global__ void fill_dct_inv(float* D, int N){
    int i = blockIdx.x*blockDim.x + threadIdx.x;
    if (i < N*N){
        int n = i / N, k = i % N;
        if (k == 0) D[i] = 1.0f / (float)(2*N);
        else {
            int r = ((2*n+1)*k) % (4*N);
            D[i] = cospif((float)r / (float)(2*N)) / (float)N;
        }
    }
}

// ---------------- NHWC -> NCHW transpose -------------------------------------
__global__ __launch_bounds__(256) void transpose_in(const float* __restrict__ x){
    __shared__ float s[32*28];
    int blk = blockIdx.x;
    int b   = blk / (HWSZ/32);
    int hw0 = (blk % (HWSZ/32)) * 32;
    const float* src = x + ((long)b*HWSZ + hw0)*CCH;
    for (int idx = threadIdx.x; idx < 32*CCH; idx += blockDim.x) s[idx] = src[idx];
    __syncthreads();
    for (int idx = threadIdx.x; idx < 32*CCH; idx += blockDim.x){
        int c = idx / 32, i = idx % 32;
        g_xn[((long)b*CCH + c)*HWSZ + hw0 + i] = s[i*CCH + c];
    }
}

// ---------------- batched tensor-core GEMM (bf16 2-term split) ----------------
// C[m,n] = sum_k A[m,k]*B[k,n]        (TB=false)
// C[m,n] = sum_k A[m,k]*B[n,k]        (TB=true)
// Split: X = Xh + Xl (bf16 each); C ≈ Ah*Bh + Al*Bh + Ah*Bl (fp32 accum).
// Block tile 64x64, K-step 16, 8 warps: warp w -> m-half (w&1)*32, n-quarter (w>>1)*16.
template<bool TB>
__global__ __launch_bounds__(256) void gemm_tc(
    const float* __restrict__ A, int lda, long sA,
    const float* __restrict__ B, int ldb, long sB,
    float* __restrict__ C, int ldc, long sC, int Kd)
{
    __shared__ __nv_bfloat16 sAh[64*16], sAl[64*16];   // [m][k]
    __shared__ __nv_bfloat16 sBh[64*16], sBl[64*16];   // TB=false: [k][n] (16x64); TB=true: [n][k] (64x16)

    long z = blockIdx.z;
    A += z*sA; B += z*sB; C += z*sC;
    int m0 = blockIdx.y*64, n0 = blockIdx.x*64;
    int t = threadIdx.x;
    int w = t >> 5;
    int wm = (w & 1)*32;
    int wn = (w >> 1)*16;

    wmma::fragment<wmma::accumulator,16,16,16,float> acc0, acc1;
    wmma::fill_fragment(acc0, 0.f);
    wmma::fill_fragment(acc1, 0.f);

    for (int k0 = 0; k0 < Kd; k0 += 16){
        // stage A 64x16 -> sA[m][k]
        {
            int m = t >> 2, k4 = (t & 3) << 2;
            float4 a4 = *reinterpret_cast<const float4*>(A + (m0+m)*lda + k0 + k4);
            float av[4] = {a4.x, a4.y, a4.z, a4.w};
#pragma unroll
            for (int i=0;i<4;i++){
                __nv_bfloat16 hv = __float2bfloat16(av[i]);
                sAh[m*16 + k4 + i] = hv;
                sAl[m*16 + k4 + i] = __float2bfloat16(av[i] - __bfloat162float(hv));
            }
        }
        // stage B
        if (TB){
            // B row-major [N,K]: tile rows n0..n0+63, cols k0..k0+15 -> sB[n][k]
            int n = t >> 2, k4 = (t & 3) << 2;
            float4 b4 = *reinterpret_cast<const float4*>(B + (n0+n)*ldb + k0 + k4);
            float bv[4] = {b4.x, b4.y, b4.z, b4.w};
#pragma unroll
            for (int i=0;i<4;i++){
                __nv_bfloat16 hv = __float2bfloat16(bv[i]);
                sBh[n*16 + k4 + i] = hv;
                sBl[n*16 + k4 + i] = __float2bfloat16(bv[i] - __bfloat162float(hv));
            }
        } else {
            // B row-major [K,N]: tile rows k0..k0+15, cols n0..n0+63 -> sB[k][n]
            int k = t >> 4, n4 = (t & 15) << 2;
            float4 b4 = *reinterpret_cast<const float4*>(B + (k0+k)*ldb + n0 + n4);
            float bv[4] = {b4.x, b4.y, b4.z, b4.w};
#pragma unroll
            for (int i=0;i<4;i++){
                __nv_bfloat16 hv = __float2bfloat16(bv[i]);
                sBh[k*64 + n4 + i] = hv;
                sBl[k*64 + n4 + i] = __float2bfloat16(bv[i] - __bfloat162float(hv));
            }
        }
        __syncthreads();

        wmma::fragment<wmma::matrix_a,16,16,16,__nv_bfloat16,wmma::row_major> ah, al;
        if (TB){
            wmma::fragment<wmma::matrix_b,16,16,16,__nv_bfloat16,wmma::col_major> bh, bl;
            wmma::load_matrix_sync(bh, &sBh[wn*16], 16);
            wmma::load_matrix_sync(bl, &sBl[wn*16], 16);
            wmma::load_matrix_sync(ah, &sAh[(wm+0)*16], 16);
            wmma::load_matrix_sync(al, &sAl[(wm+0)*16], 16);
            wmma::mma_sync(acc0, ah, bh, acc0);
            wmma::mma_sync(acc0, al, bh, acc0);
            wmma::mma_sync(acc0, ah, bl, acc0);
            wmma::load_matrix_sync(ah, &sAh[(wm+16)*16], 16);
            wmma::load_matrix_sync(al, &sAl[(wm+16)*16], 16);
            wmma::mma_sync(acc1, ah, bh, acc1);
            wmma::mma_sync(acc1, al, bh, acc1);
            wmma::mma_sync(acc1, ah, bl, acc1);
        } else {
            wmma::fragment<wmma::matrix_b,16,16,16,__nv_bfloat16,wmma::row_major> bh, bl;
            wmma::load_matrix_sync(bh, &sBh[wn], 64);
            wmma::load_matrix_sync(bl, &sBl[wn], 64);
            wmma::load_matrix_sync(ah, &sAh[(wm+0)*16], 16);
            wmma::load_matrix_sync(al, &sAl[(wm+0)*16], 16);
            wmma::mma_sync(acc0, ah, bh, acc0);
            wmma::mma_sync(acc0, al, bh, acc0);
            wmma::mma_sync(acc0, ah, bl, acc0);
            wmma::load_matrix_sync(ah, &sAh[(wm+16)*16], 16);
            wmma::load_matrix_sync(al, &sAl[(wm+16)*16], 16);
            wmma::mma_sync(acc1, ah, bh, acc1);
            wmma::mma_sync(acc1, al, bh, acc1);
            wmma::mma_sync(acc1, ah, bl, acc1);
        }
        __syncthreads();
    }
    wmma::store_matrix_sync(C + (long)(m0+wm+ 0)*ldc + n0 + wn, acc0, ldc, wmma::mem_row_major);
    wmma::store_matrix_sync(C + (long)(m0+wm+16)*ldc + n0 + wn, acc1, ldc, wmma::mem_row_major);
}

// ---------------- spectral attention -----------------------------------------
// Logits: DIRECT per-head q,k projection (accurate: no gram cancellation).
// Value path collapsed: U_h = A_h^T P_h;  Macc += Wv_h U_h;  out = X Macc + pb.
__global__ __launch_bounds__(256) void spec_attn_kernel(
    const float* __restrict__ wq, const float* __restrict__ wk,
    const float* __restrict__ wv, const float* __restrict__ rescale,
    const float* __restrict__ pw, const float* __restrict__ pb)
{
    __shared__ float X[64*29];            // [m][c]
    __shared__ float qs[28*65], ks[28*65];// [d][m]
    __shared__ float attn[28*29];         // [d][e]
    __shared__ float wqs[784], wks[784], wvs[784], pws[784];
    __shared__ float U[784], Macc[784];
    __shared__ float invq[28], invk[28];

    int blk = blockIdx.x;
    int b = blk / 1280;
    int n = blk % 1280;
    int ph = n / 40, pwi = n % 40;
    int t = threadIdx.x;
    long base = (long)b*CCH*HWSZ + (long)ph*8*WW + pwi*8;

    for (int idx = t; idx < 1792; idx += 256){
        int c = idx >> 6, m = idx & 63;
        X[m*29 + c] = g_xdct[base + (long)c*HWSZ + (m>>3)*WW + (m&7)];
    }
    for (int idx = t; idx < 784; idx += 256) Macc[idx] = 0.f;

    for (int h = 0; h < 8; h++){
        __syncthreads();
        for (int idx = t; idx < 784; idx += 256){
            int c = idx / 28, d = idx % 28;
            int col = h*28 + d;
            wqs[idx] = wq[c*224 + col];
            wks[idx] = wk[c*224 + col];
            wvs[idx] = wv[c*224 + col];   // wvs[c][e]
            pws[d*28 + c] = pw[col*28 + c];  // pws[d][c'] = P[h*28+d, c']
        }
        __syncthreads();
        // q,k projections: out [d][m]
        if (t < 224){
            int d0 = (t >> 4) * 2;
            int m0 = (t & 15) * 4;
            float aq[2][4], ak[2][4];
#pragma unroll
            for (int i=0;i<2;i++)
#pragma unroll
                for (int j=0;j<4;j++){ aq[i][j]=0.f; ak[i][j]=0.f; }
#pragma unroll 4
            for (int c = 0; c < 28; c++){
                float xv[4];
#pragma unroll
                for (int j=0;j<4;j++) xv[j] = X[(m0+j)*29 + c];
                float w0q = wqs[c*28+d0], w1q = wqs[c*28+d0+1];
                float w0k = wks[c*28+d0], w1k = wks[c*28+d0+1];
#pragma unroll
                for (int j=0;j<4;j++){
                    aq[0][j] += xv[j]*w0q; aq[1][j] += xv[j]*w1q;
                    ak[0][j] += xv[j]*w0k; ak[1][j] += xv[j]*w1k;
                }
            }
#pragma unroll
            for (int i=0;i<2;i++)
#pragma unroll
                for (int j=0;j<4;j++){
                    qs[(d0+i)*65 + m0+j] = aq[i][j];
                    ks[(d0+i)*65 + m0+j] = ak[i][j];
                }
        }
        __syncthreads();
        // l2 norms along m
        if (t < 56){
            int d = t % 28;
            float* p = (t < 28) ? qs : ks;
            float s = 0.f;
#pragma unroll 8
            for (int m=0;m<64;m++){ float v = p[d*65+m]; s += v*v; }
            float inv = 1.0f / fmaxf(sqrtf(s), 1e-12f);
            if (t < 28) invq[d] = inv; else invk[d] = inv;
        }
        __syncthreads();
        // attn[d][e]
        float rs = rescale[h];
        if (t < 196){
            int d0 = (t / 14) * 2;
            int e0 = (t % 14) * 2;
            float a00=0,a01=0,a10=0,a11=0;
#pragma unroll 8
            for (int m=0;m<64;m++){
                float q0 = qs[d0*65+m], q1 = qs[(d0+1)*65+m];
                float k0 = ks[e0*65+m], k1 = ks[(e0+1)*65+m];
                a00 += q0*k0; a01 += q0*k1; a10 += q1*k0; a11 += q1*k1;
            }
            attn[d0*29 + e0]       = a00*invq[d0]  *invk[e0]  *rs;
            attn[d0*29 + e0+1]     = a01*invq[d0]  *invk[e0+1]*rs;
            attn[(d0+1)*29 + e0]   = a10*invq[d0+1]*invk[e0]  *rs;
            attn[(d0+1)*29 + e0+1] = a11*invq[d0+1]*invk[e0+1]*rs;
        }
        __syncthreads();
        // softmax over e
        if (t < 28){
            float* row = attn + t*29;
            float mx = row[0];
#pragma unroll
            for (int e=1;e<28;e++) mx = fmaxf(mx, row[e]);
            float s = 0.f;
#pragma unroll
            for (int e=0;e<28;e++){ float ev = expf(row[e]-mx); row[e]=ev; s += ev; }
            float invs = 1.0f/s;
#pragma unroll
            for (int e=0;e<28;e++) row[e] *= invs;
        }
        __syncthreads();
        // U[e][c'] = sum_d A[d][e] * pws[d][c']
        for (int idx = t; idx < 784; idx += 256){
            int e = idx / 28, cp = idx % 28;
            float s = 0.f;
#pragma unroll
            for (int d = 0; d < 28; d++) s += attn[d*29+e]*pws[d*28+cp];
            U[idx] = s;
        }
        __syncthreads();
        // Macc[c][c'] += sum_e wvs[c][e]*U[e][c']
        for (int idx = t; idx < 784; idx += 256){
            int c = idx / 28, cp = idx % 28;
            float s = 0.f;
#pragma unroll
            for (int e = 0; e < 28; e++) s += wvs[c*28+e]*U[e*28+cp];
            Macc[idx] += s;
        }
    }
    __syncthreads();
    // out = X @ Macc + pb  -> g_xlow
    for (int idx = t; idx < 1792; idx += 256){
        int m = idx / 28, cp = idx % 28;
        float s = pb[cp];
#pragma unroll
        for (int c = 0; c < 28; c++) s += X[m*29+c]*Macc[c*28+cp];
        g_xlow[base + (long)cp*HWSZ + (m>>3)*WW + (m&7)] = s;
    }
}

// ---------------- local attention fused-weight precompute --------------------
__global__ void loc_fuse_kernel(const float* __restrict__ wq,
                                const float* __restrict__ wkv,
                                const float* __restrict__ pw)
{
    int idx = blockIdx.x*blockDim.x + threadIdx.x;
    const float qscale = 0.18898223650461363f; // 28^-0.5
    if (idx < 6272){
        int h = idx / 784, r = idx % 784;
        int c = r / 28, c2 = r % 28;
        float s = 0.f;
#pragma unroll
        for (int d = 0; d < 28; d++)
            s += wq[c*224 + h*28 + d] * wkv[c2*448 + h*28 + d];
        g_gqk[idx] = s * qscale;
    } else if (idx < 12544){
        int i2 = idx - 6272;
        int h = i2 / 784, r = i2 % 784;
        int c = r / 28, cp = r % 28;
        float s = 0.f;
#pragma unroll
        for (int d = 0; d < 28; d++)
            s += wkv[c*448 + 224 + h*28 + d] * pw[(h*28 + d)*28 + cp];
        g_wvp[i2] = s;
    }
}

// ---------------- windowed local attention (fused weights) -------------------
__global__ __launch_bounds__(256) void local_attn_kernel(
    const float* __restrict__ x, const float* __restrict__ pos,
    const float* __restrict__ pb)
{
    extern __shared__ float sm[];
    float* X   = sm;            // [64][29]
    float* T   = X   + 64*29;   // [64][29]  X @ gqk_h
    float* V2  = T   + 64*29;   // [64][29]  X @ wvp_h
    float* sim = V2  + 64*29;   // [64][65]
    float* oacc= sim + 64*65;   // [64][29]
    float* wg  = oacc+ 64*29;   // 784
    float* wv2 = wg  + 784;     // 784

    int blk = blockIdx.x;
    int b = blk / 1280;
    int n = blk % 1280;
    int ph = n / 40, pwi = n % 40;
    int t = threadIdx.x;
    long basex = (((long)b*HH + ph*8)*WW + pwi*8)*CCH;

    for (int idx = t; idx < 1792; idx += 256){
        int i = idx / 28, c = idx % 28;
        X[i*29 + c] = x[basex + ((i>>3)*WW + (i&7))*CCH + c];
    }
    for (int idx = t; idx < 1792; idx += 256){
        int m = idx / 28, c = idx % 28;
        oacc[m*29 + c] = pb[c];
    }

    for (int h = 0; h < 8; h++){
        __syncthreads();
        for (int idx = t; idx < 784; idx += 256){
            wg[idx]  = g_gqk[h*784 + idx];
            wv2[idx] = g_wvp[h*784 + idx];
        }
        __syncthreads();
        // T = X@wg, V2 = X@wv2
        if (t < 224){
            int i0 = (t & 15) * 4;
            int d0 = (t >> 4) * 2;
            float aT[4][2], aV[4][2];
#pragma unroll
            for (int i=0;i<4;i++){ aT[i][0]=aT[i][1]=aV[i][0]=aV[i][1]=0.f; }
#pragma unroll 4
            for (int c=0;c<28;c++){
                float xv[4];
#pragma unroll
                for (int i=0;i<4;i++) xv[i] = X[(i0+i)*29 + c];
                float g0 = wg[c*28+d0],  g1 = wg[c*28+d0+1];
                float v0 = wv2[c*28+d0], v1 = wv2[c*28+d0+1];
#pragma unroll
                for (int i=0;i<4;i++){
                    aT[i][0]+=xv[i]*g0; aT[i][1]+=xv[i]*g1;
                    aV[i][0]+=xv[i]*v0; aV[i][1]+=xv[i]*v1;
                }
            }
#pragma unroll
            for (int i=0;i<4;i++){
                T [(i0+i)*29 + d0]   = aT[i][0];
                T [(i0+i)*29 + d0+1] = aT[i][1];
                V2[(i0+i)*29 + d0]   = aV[i][0];
                V2[(i0+i)*29 + d0+1] = aV[i][1];
            }
        }
        __syncthreads();
        // sim[i][j] = T[i][:] . X[j][:] + pos
        {
            int i0 = (t >> 4) * 4;
            int j0 = (t & 15) * 4;
            float acc[4][4];
#pragma unroll
            for (int i=0;i<4;i++)
#pragma unroll
                for (int j=0;j<4;j++) acc[i][j]=0.f;
#pragma unroll 4
            for (int d=0;d<28;d++){
                float qv[4], kv[4];
#pragma unroll
                for (int i=0;i<4;i++) qv[i] = T[(i0+i)*29 + d];
#pragma unroll
                for (int j=0;j<4;j++) kv[j] = X[(j0+j)*29 + d];
#pragma unroll
                for (int i=0;i<4;i++)
#pragma unroll
                    for (int j=0;j<4;j++) acc[i][j] += qv[i]*kv[j];
            }
            const float* ph2 = pos + h*4096;
#pragma unroll
            for (int i=0;i<4;i++)
#pragma unroll
                for (int j=0;j<4;j++)
                    sim[(i0+i)*65 + j0+j] = acc[i][j] + ph2[(i0+i)*64 + j0+j];
        }
        __syncthreads();
        // softmax rows
        if (t < 64){
            float* row = sim + t*65;
            float mx = row[0];
#pragma unroll 8
            for (int j=1;j<64;j++) mx = fmaxf(mx, row[j]);
            float s = 0.f;
#pragma unroll 8
            for (int j=0;j<64;j++){ float ev = expf(row[j]-mx); row[j]=ev; s+=ev; }
            float invs = 1.0f/s;
#pragma unroll 8
            for (int j=0;j<64;j++) row[j] *= invs;
        }
        __syncthreads();
        // oacc[i][c] += sum_j A[i][j] * V2[j][c]
        if (t < 224){
            int i0 = (t & 15) * 4;
            int c0 = (t >> 4) * 2;
            float acc[4][2];
#pragma unroll
            for (int i=0;i<4;i++){ acc[i][0]=0.f; acc[i][1]=0.f; }
#pragma unroll 4
            for (int j=0;j<64;j++){
                float v0 = V2[j*29 + c0], v1 = V2[j*29 + c0+1];
                float sv[4];
#pragma unroll
                for (int i=0;i<4;i++) sv[i] = sim[(i0+i)*65 + j];
#pragma unroll
                for (int i=0;i<4;i++){ acc[i][0]+=sv[i]*v0; acc[i][1]+=sv[i]*v1; }
            }
#pragma unroll
            for (int i=0;i<4;i++){
                oacc[(i0+i)*29 + c0]   += acc[i][0];
                oacc[(i0+i)*29 + c0+1] += acc[i][1];
            }
        }
    }
    __syncthreads();
    for (int idx = t; idx < 1792; idx += 256){
        int c = idx >> 6, m = idx & 63;
        g_loc[((long)b*CCH + c)*HWSZ + (ph*8 + (m>>3))*WW + pwi*8 + (m&7)] = oacc[m*29 + c];
    }
}

// ---------------- high-frequency conv path -----------------------------------
__global__ __launch_bounds__(256) void pw1_gelu_kernel(const float* __restrict__ W){
    __shared__ float Ws[784];
    for (int idx = threadIdx.x; idx < 784; idx += 256) Ws[idx] = W[idx];
    __syncthreads();
    int p = blockIdx.x*256 + threadIdx.x;
    int b = p / HWSZ; int hw = p % HWSZ;
    long base = (long)b*CCH*HWSZ + hw;
    float xin[28];
#pragma unroll
    for (int c=0;c<28;c++) xin[c] = g_xdct[base + (long)c*HWSZ];
#pragma unroll 2
    for (int o=0;o<28;o++){
        float s = 0.f;
#pragma unroll
        for (int c=0;c<28;c++) s += Ws[o*28+c]*xin[c];
        g_xn[base + (long)o*HWSZ] = gelu_f(s);
    }
}

__global__ __launch_bounds__(256) void dw_gelu_add_kernel(const float* __restrict__ Wd){
    int id = blockIdx.x*256 + threadIdx.x;
    if (id >= NELEM) return;
    int w = id % WW;
    int r1 = id / WW;
    int h = r1 % HH;
    int bc = r1 / HH;
    int c = bc % CCH;
    float acc = 0.f;
#pragma unroll
    for (int dh=-1; dh<=1; dh++){
        int hy = h + dh;
        if (hy < 0 || hy >= HH) continue;
#pragma unroll
        for (int dw2=-1; dw2<=1; dw2++){
            int wx = w + dw2;
            if (wx < 0 || wx >= WW) continue;
            acc += g_xn[((long)bc*HH + hy)*WW + wx] * Wd[c*9 + (dh+1)*3 + (dw2+1)];
        }
    }
    g_xconv[id] = gelu_f(acc) + g_xdct[id];
}

__global__ __launch_bounds__(256) void combine_kernel(
    const float* __restrict__ W2, const float* __restrict__ coef)
{
    __shared__ float Ws[784];
    for (int idx = threadIdx.x; idx < 784; idx += 256) Ws[idx] = W2[idx];
    __syncthreads();
    int p = blockIdx.x*256 + threadIdx.x;
    int b = p / HWSZ; int hw = p % HWSZ;
    long base = (long)b*CCH*HWSZ + hw;
    float xc[28];
#pragma unroll
    for (int c=0;c<28;c++) xc[c] = g_xconv[base + (long)c*HWSZ];
    float cf = coef[hw];
#pragma unroll 2
    for (int o=0;o<28;o++){
        float s = 0.f;
#pragma unroll
        for (int c=0;c<28;c++) s += Ws[o*28+c]*xc[c];
        float th = gelu_f(s) + xc[o];
        long off = base + (long)o*HWSZ;
        g_xout[off] = cf*g_xlow[off] + (1.0f-cf)*th + g_xdct[off];
    }
}

// ---------------- fusion ------------------------------------------------------
__global__ __launch_bounds__(256) void fusion_kernel(
    const float* __restrict__ fw, const float* __restrict__ fb,
    float* __restrict__ out)
{
    __shared__ float Ws[28*56];
    __shared__ float fbs[28];
    __shared__ float so[256*28];
    for (int idx = threadIdx.x; idx < 28*56; idx += 256) Ws[idx] = fw[idx];
    if (threadIdx.x < 28) fbs[threadIdx.x] = fb[threadIdx.x];
    __syncthreads();
    int p = blockIdx.x*256 + threadIdx.x;
    int b = p / HWSZ; int hw = p % HWSZ;
    long base = (long)b*CCH*HWSZ + hw;
    float fd[28], lc[28];
#pragma unroll
    for (int c=0;c<28;c++){
        fd[c] = g_fd[base + (long)c*HWSZ];
        lc[c] = g_loc[base + (long)c*HWSZ];
    }
#pragma unroll 2
    for (int o=0;o<28;o++){
        float s = fbs[o];
#pragma unroll
        for (int c=0;c<28;c++) s += Ws[o*56 + c]*fd[c] + Ws[o*56 + 28 + c]*lc[c];
        so[threadIdx.x*28 + o] = s;
    }
    __syncthreads();
    long obase = (long)blockIdx.x*256*28;
    for (int idx = threadIdx.x; idx < 256*28; idx += 256) out[obase + idx] = so[idx];
}

// ---------------- launch ------------------------------------------------------
extern "C" void kernel_launch(void* const* d_in, const int* in_sizes, int n_in,
                              void* d_out, int out_size)
{
    const float* x          = (const float*)d_in[0];
    const float* spec_wq    = (const float*)d_in[1];
    const float* spec_wk    = (const float*)d_in[2];
    const float* spec_wv    = (const float*)d_in[3];
    const float* spec_rs    = (const float*)d_in[4];
    const float* spec_pw    = (const float*)d_in[5];
    const float* spec_pb    = (const float*)d_in[6];
    const float* hf1_pw_w   = (const float*)d_in[7];
    const float* hf1_dw_w   = (const float*)d_in[8];
    const float* hf2_pw_w   = (const float*)d_in[9];
    const float* coef_emb   = (const float*)d_in[10];
    const float* loc_wq     = (const float*)d_in[11];
    const float* loc_wkv    = (const float*)d_in[12];
    const float* loc_pos    = (const float*)d_in[13];
    const float* loc_pw     = (const float*)d_in[14];
    const float* loc_pb     = (const float*)d_in[15];
    const float* fus_w      = (const float*)d_in[16];
    const float* fus_b      = (const float*)d_in[17];
    float* out = (float*)d_out;

    float *p_xn, *p_tmp, *p_xdct, *p_xout, *p_fd;
    float *p_DH, *p_DW, *p_DIH, *p_DIW;
    cudaGetSymbolAddress((void**)&p_xn,   g_xn);
    cudaGetSymbolAddress((void**)&p_tmp,  g_tmp);
    cudaGetSymbolAddress((void**)&p_xdct, g_xdct);
    cudaGetSymbolAddress((void**)&p_xout, g_xout);
    cudaGetSymbolAddress((void**)&p_fd,   g_fd);
    cudaGetSymbolAddress((void**)&p_DH,   g_DH);
    cudaGetSymbolAddress((void**)&p_DW,   g_DW);
    cudaGetSymbolAddress((void**)&p_DIH,  g_DIH);
    cudaGetSymbolAddress((void**)&p_DIW,  g_DIW);

    const int LOCAL_SMEM = 13152 * 4;   // 52608 B
    cudaFuncSetAttribute(local_attn_kernel, cudaFuncAttributeMaxDynamicSharedMemorySize, LOCAL_SMEM);

    // DCT matrices
    fill_dct_fwd<<<(256*256+255)/256, 256>>>(p_DH, 256);
    fill_dct_fwd<<<(320*320+255)/256, 256>>>(p_DW, 320);
    fill_dct_inv<<<(256*256+255)/256, 256>>>(p_DIH, 256);
    fill_dct_inv<<<(320*320+255)/256, 256>>>(p_DIW, 320);

    // NHWC -> NCHW
    transpose_in<<<NB*(HWSZ/32), 256>>>(x);

    // forward 2D DCT: tmp = D_H * xn ; xdct = tmp * D_W^T   (batched over b*c=56)
    gemm_tc<false><<<dim3(5,4,56), 256>>>(p_DH, 256, 0,  p_xn, 320, HWSZ,
                                          p_tmp, 320, HWSZ, 256);
    gemm_tc<true ><<<dim3(5,4,56), 256>>>(p_tmp, 320, HWSZ, p_DW, 320, 0,
                                          p_xdct, 320, HWSZ, 320);

    // spectral attention branch -> g_xlow
    spec_attn_kernel<<<2560, 256>>>(spec_wq, spec_wk, spec_wv,
                                    spec_rs, spec_pw, spec_pb);

    // high-frequency path
    pw1_gelu_kernel<<<NPIX/256, 256>>>(hf1_pw_w);
    dw_gelu_add_kernel<<<(NELEM+255)/256, 256>>>(hf1_dw_w);
    combine_kernel<<<NPIX/256, 256>>>(hf2_pw_w, coef_emb);

    // inverse 2D DCT: tmp = DI_H * xout ; fd = tmp * DI_W^T
    gemm_tc<false><<<dim3(5,4,56), 256>>>(p_DIH, 256, 0, p_xout, 320, HWSZ,
                                          p_tmp, 320, HWSZ, 256);
    gemm_tc<true ><<<dim3(5,4,56), 256>>>(p_tmp, 320, HWSZ, p_DIW, 320, 0,
                                          p_fd, 320, HWSZ, 320);

    // local attention branch -> g_loc (fused weights precomputed)
    loc_fuse_kernel<<<(12544+255)/256, 256>>>(loc_wq, loc_wkv, loc_pw);
    local_attn_kernel<<<2560, 256, LOCAL_SMEM>>>(x, loc_pos, loc_pb);

    // fusion -> NHWC output
    fusion_kernel<<<NPIX/256, 256>>>(fus_w, fus_b, out);
}

// round 7
// speedup vs baseline: 1.1350x; 1.0017x over previous
#include <cuda_runtime.h>
#include <cuda_bf16.h>
#include <mma.h>
#include <math.h>

using namespace nvcuda;

#define HH 256
#define WW 320
#define CCH 28
#define HWSZ (HH*WW)          // 81920
#define NB 2
#define NELEM (NB*CCH*HWSZ)   // 4587520
#define NPIX (NB*HWSZ)        // 163840

// ---------------- scratch (static device globals; no runtime allocation) -----
__device__ float g_xn[NELEM];     // hf1 output (y) buffer
__device__ float g_tmp[NELEM];    // DCT pass-1 intermediate (fp32 gemm out)
__device__ float g_xdct[NELEM];   // DCT of input
__device__ float g_xlow[NELEM];   // spectral attention branch out (NCHW)
__device__ float g_xconv[NELEM];  // dw-conv + residual
__device__ float g_fd[NELEM];     // out_fd (NCHW)
__device__ float g_loc[NELEM];    // out_local (NCHW)
__device__ float g_gqk[8*784];    // fused local-attn  s * Wq Wk^T  per head
__device__ float g_wvp[8*784];    // fused local-attn  Wv @ P       per head

// split-bf16 operands for tensor-core GEMMs
__device__ __nv_bfloat16 g_DHh[256*256],  g_DHl[256*256];
__device__ __nv_bfloat16 g_DWh[320*320],  g_DWl[320*320];
__device__ __nv_bfloat16 g_DIHh[256*256], g_DIHl[256*256];
__device__ __nv_bfloat16 g_DIWh[320*320], g_DIWl[320*320];
__device__ __nv_bfloat16 g_xnh[NELEM],  g_xnl[NELEM];
__device__ __nv_bfloat16 g_tmph[NELEM], g_tmpl[NELEM];
__device__ __nv_bfloat16 g_xoh[NELEM],  g_xol[NELEM];

__device__ __forceinline__ float gelu_f(float x){
    return 0.5f*x*(1.0f + erff(x*0.7071067811865476f));
}
__device__ __forceinline__ void split2(float v, __nv_bfloat16& h, __nv_bfloat16& l){
    h = __float2bfloat16(v);
    l = __float2bfloat16(v - __bfloat162float(h));
}

// ---------------- DCT matrix generation (direct split-bf16 output) -----------
__global__ void fill_dct_fwd(__nv_bfloat16* Dh, __nv_bfloat16* Dl, int N){
    int i = blockIdx.x*blockDim.x + threadIdx.x;
    if (i < N*N){
        int k = i / N, n = i % N;
        int r = ((2*n+1)*k) % (4*N);
        float v = 2.0f * cospif((float)r / (float)(2*N));
        split2(v, Dh[i], Dl[i]);
    }
}
__global__ void fill_dct_inv(__nv_bfloat16* Dh, __nv_bfloat16* Dl, int N){
    int i = blockIdx.x*blockDim.x + threadIdx.x;
    if (i < N*N){
        int n = i / N, k = i % N;
        float v;
        if (k == 0) v = 1.0f / (float)(2*N);
        else {
            int r = ((2*n+1)*k) % (4*N);
            v = cospif((float)r / (float)(2*N)) / (float)N;
        }
        split2(v, Dh[i], Dl[i]);
    }
}

// ---------------- fp32 -> split bf16 (vectorized) -----------------------------
__global__ __launch_bounds__(256) void convert_split(const float* __restrict__ src,
                                                     __nv_bfloat16* __restrict__ h,
                                                     __nv_bfloat16* __restrict__ l){
    long i = ((long)blockIdx.x*256 + threadIdx.x)*4;
    float4 v = *reinterpret_cast<const float4*>(src + i);
    __nv_bfloat16 h0,h1,h2,h3,l0,l1,l2,l3;
    split2(v.x,h0,l0); split2(v.y,h1,l1); split2(v.z,h2,l2); split2(v.w,h3,l3);
    __nv_bfloat162* ph = reinterpret_cast<__nv_bfloat162*>(h + i);
    __nv_bfloat162* pl = reinterpret_cast<__nv_bfloat162*>(l + i);
    ph[0] = __nv_bfloat162{h0,h1}; ph[1] = __nv_bfloat162{h2,h3};
    pl[0] = __nv_bfloat162{l0,l1}; pl[1] = __nv_bfloat162{l2,l3};
}

// ---------------- NHWC -> NCHW transpose (emits split bf16) -------------------
__global__ __launch_bounds__(256) void transpose_in(const float* __restrict__ x){
    __shared__ float s[32*28];
    int blk = blockIdx.x;
    int b   = blk / (HWSZ/32);
    int hw0 = (blk % (HWSZ/32)) * 32;
    const float* src = x + ((long)b*HWSZ + hw0)*CCH;
    for (int idx = threadIdx.x; idx < 32*CCH; idx += blockDim.x) s[idx] = src[idx];
    __syncthreads();
    for (int idx = threadIdx.x; idx < 32*CCH; idx += blockDim.x){
        int c = idx / 32, i = idx % 32;
        long o = ((long)b*CCH + c)*HWSZ + hw0 + i;
        split2(s[i*CCH + c], g_xnh[o], g_xnl[o]);
    }
}

// ---------------- batched tensor-core GEMM (preconverted split bf16) ----------
// C[m,n] = sum_k A[m,k]*B[k,n]  (TB=false)  |  C[m,n] = sum_k A[m,k]*B[n,k]  (TB=true)
// C ≈ Ah*Bh + Al*Bh + Ah*Bl  (fp32 accum). Block 64x64, k-step 16, 8 warps.
template<bool TB>
__global__ __launch_bounds__(256) void gemm_tcs(
    const __nv_bfloat16* __restrict__ Ah, const __nv_bfloat16* __restrict__ Al, int lda, long sA,
    const __nv_bfloat16* __restrict__ Bh, const __nv_bfloat16* __restrict__ Bl, int ldb, long sB,
    float* __restrict__ C, int ldc, long sC, int Kd)
{
    __shared__ __nv_bfloat16 sAh[64*16], sAl[64*16];
    __shared__ __nv_bfloat16 sBh[64*16], sBl[64*16];

    long z = blockIdx.z;
    Ah += z*sA; Al += z*sA; Bh += z*sB; Bl += z*sB; C += z*sC;
    int m0 = blockIdx.y*64, n0 = blockIdx.x*64;
    int t = threadIdx.x;
    int w = t >> 5;
    int wm = (w & 1)*32;
    int wn = (w >> 1)*16;

    wmma::fragment<wmma::accumulator,16,16,16,float> acc0, acc1;
    wmma::fill_fragment(acc0, 0.f);
    wmma::fill_fragment(acc1, 0.f);

    for (int k0 = 0; k0 < Kd; k0 += 16){
        {
            int m = t >> 2, k4 = (t & 3) << 2;
            long off = (long)(m0+m)*lda + k0 + k4;
            *reinterpret_cast<uint2*>(&sAh[m*16+k4]) = *reinterpret_cast<const uint2*>(Ah + off);
            *reinterpret_cast<uint2*>(&sAl[m*16+k4]) = *reinterpret_cast<const uint2*>(Al + off);
        }
        if (TB){
            int n = t >> 2, k4 = (t & 3) << 2;
            long off = (long)(n0+n)*ldb + k0 + k4;
            *reinterpret_cast<uint2*>(&sBh[n*16+k4]) = *reinterpret_cast<const uint2*>(Bh + off);
            *reinterpret_cast<uint2*>(&sBl[n*16+k4]) = *reinterpret_cast<const uint2*>(Bl + off);
        } else {
            int k = t >> 4, n4 = (t & 15) << 2;
            long off = (long)(k0+k)*ldb + n0 + n4;
            *reinterpret_cast<uint2*>(&sBh[k*64+n4]) = *reinterpret_cast<const uint2*>(Bh + off);
            *reinterpret_cast<uint2*>(&sBl[k*64+n4]) = *reinterpret_cast<const uint2*>(Bl + off);
        }
        __syncthreads();

        wmma::fragment<wmma::matrix_a,16,16,16,__nv_bfloat16,wmma::row_major> ah, al;
        if (TB){
            wmma::fragment<wmma::matrix_b,16,16,16,__nv_bfloat16,wmma::col_major> bh, bl;
            wmma::load_matrix_sync(bh, &sBh[wn*16], 16);
            wmma::load_matrix_sync(bl, &sBl[wn*16], 16);
            wmma::load_matrix_sync(ah, &sAh[(wm+0)*16], 16);
            wmma::load_matrix_sync(al, &sAl[(wm+0)*16], 16);
            wmma::mma_sync(acc0, ah, bh, acc0);
            wmma::mma_sync(acc0, al, bh, acc0);
            wmma::mma_sync(acc0, ah, bl, acc0);
            wmma::load_matrix_sync(ah, &sAh[(wm+16)*16], 16);
            wmma::load_matrix_sync(al, &sAl[(wm+16)*16], 16);
            wmma::mma_sync(acc1, ah, bh, acc1);
            wmma::mma_sync(acc1, al, bh, acc1);
            wmma::mma_sync(acc1, ah, bl, acc1);
        } else {
            wmma::fragment<wmma::matrix_b,16,16,16,__nv_bfloat16,wmma::row_major> bh, bl;
            wmma::load_matrix_sync(bh, &sBh[wn], 64);
            wmma::load_matrix_sync(bl, &sBl[wn], 64);
            wmma::load_matrix_sync(ah, &sAh[(wm+0)*16], 16);
            wmma::load_matrix_sync(al, &sAl[(wm+0)*16], 16);
            wmma::mma_sync(acc0, ah, bh, acc0);
            wmma::mma_sync(acc0, al, bh, acc0);
            wmma::mma_sync(acc0, ah, bl, acc0);
            wmma::load_matrix_sync(ah, &sAh[(wm+16)*16], 16);
            wmma::load_matrix_sync(al, &sAl[(wm+16)*16], 16);
            wmma::mma_sync(acc1, ah, bh, acc1);
            wmma::mma_sync(acc1, al, bh, acc1);
            wmma::mma_sync(acc1, ah, bl, acc1);
        }
        __syncthreads();
    }
    wmma::store_matrix_sync(C + (long)(m0+wm+ 0)*ldc + n0 + wn, acc0, ldc, wmma::mem_row_major);
    wmma::store_matrix_sync(C + (long)(m0+wm+16)*ldc + n0 + wn, acc1, ldc, wmma::mem_row_major);
}

// ---------------- spectral attention -----------------------------------------
__global__ __launch_bounds__(256) void spec_attn_kernel(
    const float* __restrict__ wq, const float* __restrict__ wk,
    const float* __restrict__ wv, const float* __restrict__ rescale,
    const float* __restrict__ pw, const float* __restrict__ pb)
{
    __shared__ float X[64*29];            // [m][c]
    __shared__ float qs[28*65], ks[28*65];// [d][m]
    __shared__ float attn[28*29];         // [d][e]
    __shared__ float wqs[784], wks[784], wvs[784], pws[784];
    __shared__ float U[784], Macc[784];
    __shared__ float invq[28], invk[28];

    int blk = blockIdx.x;
    int b = blk / 1280;
    int n = blk % 1280;
    int ph = n / 40, pwi = n % 40;
    int t = threadIdx.x;
    long base = (long)b*CCH*HWSZ + (long)ph*8*WW + pwi*8;

    for (int idx = t; idx < 1792; idx += 256){
        int c = idx >> 6, m = idx & 63;
        X[m*29 + c] = g_xdct[base + (long)c*HWSZ + (m>>3)*WW + (m&7)];
    }
    for (int idx = t; idx < 784; idx += 256) Macc[idx] = 0.f;

    for (int h = 0; h < 8; h++){
        __syncthreads();
        for (int idx = t; idx < 784; idx += 256){
            int c = idx / 28, d = idx % 28;
            int col = h*28 + d;
            wqs[idx] = wq[c*224 + col];
            wks[idx] = wk[c*224 + col];
            wvs[idx] = wv[c*224 + col];      // wvs[c][e]
            pws[d*28 + c] = pw[col*28 + c];  // pws[d][c'] = P[h*28+d, c']
        }
        __syncthreads();
        if (t < 224){
            int d0 = (t >> 4) * 2;
            int m0 = (t & 15) * 4;
            float aq[2][4], ak[2][4];
#pragma unroll
            for (int i=0;i<2;i++)
#pragma unroll
                for (int j=0;j<4;j++){ aq[i][j]=0.f; ak[i][j]=0.f; }
#pragma unroll 4
            for (int c = 0; c < 28; c++){
                float xv[4];
#pragma unroll
                for (int j=0;j<4;j++) xv[j] = X[(m0+j)*29 + c];
                float w0q = wqs[c*28+d0], w1q = wqs[c*28+d0+1];
                float w0k = wks[c*28+d0], w1k = wks[c*28+d0+1];
#pragma unroll
                for (int j=0;j<4;j++){
                    aq[0][j] += xv[j]*w0q; aq[1][j] += xv[j]*w1q;
                    ak[0][j] += xv[j]*w0k; ak[1][j] += xv[j]*w1k;
                }
            }
#pragma unroll
            for (int i=0;i<2;i++)
#pragma unroll
                for (int j=0;j<4;j++){
                    qs[(d0+i)*65 + m0+j] = aq[i][j];
                    ks[(d0+i)*65 + m0+j] = ak[i][j];
                }
        }
        __syncthreads();
        if (t < 56){
            int d = t % 28;
            float* p = (t < 28) ? qs : ks;
            float s = 0.f;
#pragma unroll 8
            for (int m=0;m<64;m++){ float v = p[d*65+m]; s += v*v; }
            float inv = 1.0f / fmaxf(sqrtf(s), 1e-12f);
            if (t < 28) invq[d] = inv; else invk[d] = inv;
        }
        __syncthreads();
        float rs = rescale[h];
        if (t < 196){
            int d0 = (t / 14) * 2;
            int e0 = (t % 14) * 2;
            float a00=0,a01=0,a10=0,a11=0;
#pragma unroll 8
            for (int m=0;m<64;m++){
                float q0 = qs[d0*65+m], q1 = qs[(d0+1)*65+m];
                float k0 = ks[e0*65+m], k1 = ks[(e0+1)*65+m];
                a00 += q0*k0; a01 += q0*k1; a10 += q1*k0; a11 += q1*k1;
            }
            attn[d0*29 + e0]       = a00*invq[d0]  *invk[e0]  *rs;
            attn[d0*29 + e0+1]     = a01*invq[d0]  *invk[e0+1]*rs;
            attn[(d0+1)*29 + e0]   = a10*invq[d0+1]*invk[e0]  *rs;
            attn[(d0+1)*29 + e0+1] = a11*invq[d0+1]*invk[e0+1]*rs;
        }
        __syncthreads();
        if (t < 28){
            float* row = attn + t*29;
            float mx = row[0];
#pragma unroll
            for (int e=1;e<28;e++) mx = fmaxf(mx, row[e]);
            float s = 0.f;
#pragma unroll
            for (int e=0;e<28;e++){ float ev = expf(row[e]-mx); row[e]=ev; s += ev; }
            float invs = 1.0f/s;
#pragma unroll
            for (int e=0;e<28;e++) row[e] *= invs;
        }
        __syncthreads();
        for (int idx = t; idx < 784; idx += 256){
            int e = idx / 28, cp = idx % 28;
            float s = 0.f;
#pragma unroll
            for (int d = 0; d < 28; d++) s += attn[d*29+e]*pws[d*28+cp];
            U[idx] = s;
        }
        __syncthreads();
        for (int idx = t; idx < 784; idx += 256){
            int c = idx / 28, cp = idx % 28;
            float s = 0.f;
#pragma unroll
            for (int e = 0; e < 28; e++) s += wvs[c*28+e]*U[e*28+cp];
            Macc[idx] += s;
        }
    }
    __syncthreads();
    for (int idx = t; idx < 1792; idx += 256){
        int m = idx / 28, cp = idx % 28;
        float s = pb[cp];
#pragma unroll
        for (int c = 0; c < 28; c++) s += X[m*29+c]*Macc[c*28+cp];
        g_xlow[base + (long)cp*HWSZ + (m>>3)*WW + (m&7)] = s;
    }
}

// ---------------- local attention fused-weight precompute --------------------
__global__ void loc_fuse_kernel(const float* __restrict__ wq,
                                const float* __restrict__ wkv,
                                const float* __restrict__ pw)
{
    int idx = blockIdx.x*blockDim.x + threadIdx.x;
    const float qscale = 0.18898223650461363f; // 28^-0.5
    if (idx < 6272){
        int h = idx / 784, r = idx % 784;
        int c = r / 28, c2 = r % 28;
        float s = 0.f;
#pragma unroll
        for (int d = 0; d < 28; d++)
            s += wq[c*224 + h*28 + d] * wkv[c2*448 + h*28 + d];
        g_gqk[idx] = s * qscale;
    } else if (idx < 12544){
        int i2 = idx - 6272;
        int h = i2 / 784, r = i2 % 784;
        int c = r / 28, cp = r % 28;
        float s = 0.f;
#pragma unroll
        for (int d = 0; d < 28; d++)
            s += wkv[c*448 + 224 + h*28 + d] * pw[(h*28 + d)*28 + cp];
        g_wvp[i2] = s;
    }
}

// ---------------- windowed local attention (fused weights) -------------------
__global__ __launch_bounds__(256) void local_attn_kernel(
    const float* __restrict__ x, const float* __restrict__ pos,
    const float* __restrict__ pb)
{
    extern __shared__ float sm[];
    float* X   = sm;            // [64][29]
    float* T   = X   + 64*29;   // [64][29]
    float* V2  = T   + 64*29;   // [64][29]
    float* sim = V2  + 64*29;   // [64][65]
    float* oacc= sim + 64*65;   // [64][29]
    float* wg  = oacc+ 64*29;   // 784
    float* wv2 = wg  + 784;     // 784

    int blk = blockIdx.x;
    int b = blk / 1280;
    int n = blk % 1280;
    int ph = n / 40, pwi = n % 40;
    int t = threadIdx.x;
    long basex = (((long)b*HH + ph*8)*WW + pwi*8)*CCH;

    for (int idx = t; idx < 1792; idx += 256){
        int i = idx / 28, c = idx % 28;
        X[i*29 + c] = x[basex + ((i>>3)*WW + (i&7))*CCH + c];
    }
    for (int idx = t; idx < 1792; idx += 256){
        int m = idx / 28, c = idx % 28;
        oacc[m*29 + c] = pb[c];
    }

    for (int h = 0; h < 8; h++){
        __syncthreads();
        for (int idx = t; idx < 784; idx += 256){
            wg[idx]  = g_gqk[h*784 + idx];
            wv2[idx] = g_wvp[h*784 + idx];
        }
        __syncthreads();
        if (t < 224){
            int i0 = (t & 15) * 4;
            int d0 = (t >> 4) * 2;
            float aT[4][2], aV[4][2];
#pragma unroll
            for (int i=0;i<4;i++){ aT[i][0]=aT[i][1]=aV[i][0]=aV[i][1]=0.f; }
#pragma unroll 4
            for (int c=0;c<28;c++){
                float xv[4];
#pragma unroll
                for (int i=0;i<4;i++) xv[i] = X[(i0+i)*29 + c];
                float g0 = wg[c*28+d0],  g1 = wg[c*28+d0+1];
                float v0 = wv2[c*28+d0], v1 = wv2[c*28+d0+1];
#pragma unroll
                for (int i=0;i<4;i++){
                    aT[i][0]+=xv[i]*g0; aT[i][1]+=xv[i]*g1;
                    aV[i][0]+=xv[i]*v0; aV[i][1]+=xv[i]*v1;
                }
            }
#pragma unroll
            for (int i=0;i<4;i++){
                T [(i0+i)*29 + d0]   = aT[i][0];
                T [(i0+i)*29 + d0+1] = aT[i][1];
                V2[(i0+i)*29 + d0]   = aV[i][0];
                V2[(i0+i)*29 + d0+1] = aV[i][1];
            }
        }
        __syncthreads();
        {
            int i0 = (t >> 4) * 4;
            int j0 = (t & 15) * 4;
            float acc[4][4];
#pragma unroll
            for (int i=0;i<4;i++)
#pragma unroll
                for (int j=0;j<4;j++) acc[i][j]=0.f;
#pragma unroll 4
            for (int d=0;d<28;d++){
                float qv[4], kv[4];
#pragma unroll
                for (int i=0;i<4;i++) qv[i] = T[(i0+i)*29 + d];
#pragma unroll
                for (int j=0;j<4;j++) kv[j] = X[(j0+j)*29 + d];
#pragma unroll
                for (int i=0;i<4;i++)
#pragma unroll
                    for (int j=0;j<4;j++) acc[i][j] += qv[i]*kv[j];
            }
            const float* ph2 = pos + h*4096;
#pragma unroll
            for (int i=0;i<4;i++)
#pragma unroll
                for (int j=0;j<4;j++)
                    sim[(i0+i)*65 + j0+j] = acc[i][j] + ph2[(i0+i)*64 + j0+j];
        }
        __syncthreads();
        if (t < 64){
            float* row = sim + t*65;
            float mx = row[0];
#pragma unroll 8
            for (int j=1;j<64;j++) mx = fmaxf(mx, row[j]);
            float s = 0.f;
#pragma unroll 8
            for (int j=0;j<64;j++){ float ev = expf(row[j]-mx); row[j]=ev; s+=ev; }
            float invs = 1.0f/s;
#pragma unroll 8
            for (int j=0;j<64;j++) row[j] *= invs;
        }
        __syncthreads();
        if (t < 224){
            int i0 = (t & 15) * 4;
            int c0 = (t >> 4) * 2;
            float acc[4][2];
#pragma unroll
            for (int i=0;i<4;i++){ acc[i][0]=0.f; acc[i][1]=0.f; }
#pragma unroll 4
            for (int j=0;j<64;j++){
                float v0 = V2[j*29 + c0], v1 = V2[j*29 + c0+1];
                float sv[4];
#pragma unroll
                for (int i=0;i<4;i++) sv[i] = sim[(i0+i)*65 + j];
#pragma unroll
                for (int i=0;i<4;i++){ acc[i][0]+=sv[i]*v0; acc[i][1]+=sv[i]*v1; }
            }
#pragma unroll
            for (int i=0;i<4;i++){
                oacc[(i0+i)*29 + c0]   += acc[i][0];
                oacc[(i0+i)*29 + c0+1] += acc[i][1];
            }
        }
    }
    __syncthreads();
    for (int idx = t; idx < 1792; idx += 256){
        int c = idx >> 6, m = idx & 63;
        g_loc[((long)b*CCH + c)*HWSZ + (ph*8 + (m>>3))*WW + pwi*8 + (m&7)] = oacc[m*29 + c];
    }
}

// ---------------- high-frequency conv path -----------------------------------
__global__ __launch_bounds__(256) void pw1_gelu_kernel(const float* __restrict__ W){
    __shared__ float Ws[784];
    for (int idx = threadIdx.x; idx < 784; idx += 256) Ws[idx] = W[idx];
    __syncthreads();
    int p = blockIdx.x*256 + threadIdx.x;
    int b = p / HWSZ; int hw = p % HWSZ;
    long base = (long)b*CCH*HWSZ + hw;
    float xin[28];
#pragma unroll
    for (int c=0;c<28;c++) xin[c] = g_xdct[base + (long)c*HWSZ];
#pragma unroll 2
    for (int o=0;o<28;o++){
        float s = 0.f;
#pragma unroll
        for (int c=0;c<28;c++) s += Ws[o*28+c]*xin[c];
        g_xn[base + (long)o*HWSZ] = gelu_f(s);
    }
}

__global__ __launch_bounds__(256) void dw_gelu_add_kernel(const float* __restrict__ Wd){
    int id = blockIdx.x*256 + threadIdx.x;
    if (id >= NELEM) return;
    int w = id % WW;
    int r1 = id / WW;
    int h = r1 % HH;
    int bc = r1 / HH;
    int c = bc % CCH;
    float acc = 0.f;
#pragma unroll
    for (int dh=-1; dh<=1; dh++){
        int hy = h + dh;
        if (hy < 0 || hy >= HH) continue;
#pragma unroll
        for (int dw2=-1; dw2<=1; dw2++){
            int wx = w + dw2;
            if (wx < 0 || wx >= WW) continue;
            acc += g_xn[((long)bc*HH + hy)*WW + wx] * Wd[c*9 + (dh+1)*3 + (dw2+1)];
        }
    }
    g_xconv[id] = gelu_f(acc) + g_xdct[id];
}

// combine: emits SPLIT bf16 xout directly (gemm3 input)
__global__ __launch_bounds__(256) void combine_kernel(
    const float* __restrict__ W2, const float* __restrict__ coef)
{
    __shared__ float Ws[784];
    for (int idx = threadIdx.x; idx < 784; idx += 256) Ws[idx] = W2[idx];
    __syncthreads();
    int p = blockIdx.x*256 + threadIdx.x;
    int b = p / HWSZ; int hw = p % HWSZ;
    long base = (long)b*CCH*HWSZ + hw;
    float xc[28];
#pragma unroll
    for (int c=0;c<28;c++) xc[c] = g_xconv[base + (long)c*HWSZ];
    float cf = coef[hw];
#pragma unroll 2
    for (int o=0;o<28;o++){
        float s = 0.f;
#pragma unroll
        for (int c=0;c<28;c++) s += Ws[o*28+c]*xc[c];
        float th = gelu_f(s) + xc[o];
        long off = base + (long)o*HWSZ;
        float v = cf*g_xlow[off] + (1.0f-cf)*th + g_xdct[off];
        split2(v, g_xoh[off], g_xol[off]);
    }
}

// ---------------- fusion ------------------------------------------------------
__global__ __launch_bounds__(256) void fusion_kernel(
    const float* __restrict__ fw, const float* __restrict__ fb,
    float* __restrict__ out)
{
    __shared__ float Ws[28*56];
    __shared__ float fbs[28];
    __shared__ float so[256*28];
    for (int idx = threadIdx.x; idx < 28*56; idx += 256) Ws[idx] = fw[idx];
    if (threadIdx.x < 28) fbs[threadIdx.x] = fb[threadIdx.x];
    __syncthreads();
    int p = blockIdx.x*256 + threadIdx.x;
    int b = p / HWSZ; int hw = p % HWSZ;
    long base = (long)b*CCH*HWSZ + hw;
    float fd[28], lc[28];
#pragma unroll
    for (int c=0;c<28;c++){
        fd[c] = g_fd[base + (long)c*HWSZ];
        lc[c] = g_loc[base + (long)c*HWSZ];
    }
#pragma unroll 2
    for (int o=0;o<28;o++){
        float s = fbs[o];
#pragma unroll
        for (int c=0;c<28;c++) s += Ws[o*56 + c]*fd[c] + Ws[o*56 + 28 + c]*lc[c];
        so[threadIdx.x*28 + o] = s;
    }
    __syncthreads();
    long obase = (long)blockIdx.x*256*28;
    for (int idx = threadIdx.x; idx < 256*28; idx += 256) out[obase + idx] = so[idx];
}

// ---------------- launch ------------------------------------------------------
extern "C" void kernel_launch(void* const* d_in, const int* in_sizes, int n_in,
                              void* d_out, int out_size)
{
    const float* x          = (const float*)d_in[0];
    const float* spec_wq    = (const float*)d_in[1];
    const float* spec_wk    = (const float*)d_in[2];
    const float* spec_wv    = (const float*)d_in[3];
    const float* spec_rs    = (const float*)d_in[4];
    const float* spec_pw    = (const float*)d_in[5];
    const float* spec_pb    = (const float*)d_in[6];
    const float* hf1_pw_w   = (const float*)d_in[7];
    const float* hf1_dw_w   = (const float*)d_in[8];
    const float* hf2_pw_w   = (const float*)d_in[9];
    const float* coef_emb   = (const float*)d_in[10];
    const float* loc_wq     = (const float*)d_in[11];
    const float* loc_wkv    = (const float*)d_in[12];
    const float* loc_pos    = (const float*)d_in[13];
    const float* loc_pw     = (const float*)d_in[14];
    const float* loc_pb     = (const float*)d_in[15];
    const float* fus_w      = (const float*)d_in[16];
    const float* fus_b      = (const float*)d_in[17];
    float* out = (float*)d_out;

    float *p_tmp, *p_xdct, *p_fd;
    __nv_bfloat16 *p_DHh,*p_DHl,*p_DWh,*p_DWl,*p_DIHh,*p_DIHl,*p_DIWh,*p_DIWl;
    __nv_bfloat16 *p_xnh,*p_xnl,*p_tmph,*p_tmpl,*p_xoh,*p_xol;
    cudaGetSymbolAddress((void**)&p_tmp,  g_tmp);
    cudaGetSymbolAddress((void**)&p_xdct, g_xdct);
    cudaGetSymbolAddress((void**)&p_fd,   g_fd);
    cudaGetSymbolAddress((void**)&p_DHh,  g_DHh);  cudaGetSymbolAddress((void**)&p_DHl,  g_DHl);
    cudaGetSymbolAddress((void**)&p_DWh,  g_DWh);  cudaGetSymbolAddress((void**)&p_DWl,  g_DWl);
    cudaGetSymbolAddress((void**)&p_DIHh, g_DIHh); cudaGetSymbolAddress((void**)&p_DIHl, g_DIHl);
    cudaGetSymbolAddress((void**)&p_DIWh, g_DIWh); cudaGetSymbolAddress((void**)&p_DIWl, g_DIWl);
    cudaGetSymbolAddress((void**)&p_xnh,  g_xnh);  cudaGetSymbolAddress((void**)&p_xnl,  g_xnl);
    cudaGetSymbolAddress((void**)&p_tmph, g_tmph); cudaGetSymbolAddress((void**)&p_tmpl, g_tmpl);
    cudaGetSymbolAddress((void**)&p_xoh,  g_xoh);  cudaGetSymbolAddress((void**)&p_xol,  g_xol);

    const int LOCAL_SMEM = 13152 * 4;   // 52608 B
    cudaFuncSetAttribute(local_attn_kernel, cudaFuncAttributeMaxDynamicSharedMemorySize, LOCAL_SMEM);

    // DCT matrices (split bf16)
    fill_dct_fwd<<<(256*256+255)/256, 256>>>(p_DHh, p_DHl, 256);
    fill_dct_fwd<<<(320*320+255)/256, 256>>>(p_DWh, p_DWl, 320);
    fill_dct_inv<<<(256*256+255)/256, 256>>>(p_DIHh, p_DIHl, 256);
    fill_dct_inv<<<(320*320+255)/256, 256>>>(p_DIWh, p_DIWl, 320);

    // NHWC -> NCHW (split bf16)
    transpose_in<<<NB*(HWSZ/32), 256>>>(x);

    // forward 2D DCT
    gemm_tcs<false><<<dim3(5,4,56), 256>>>(p_DHh, p_DHl, 256, 0,
                                           p_xnh, p_xnl, 320, HWSZ,
                                           p_tmp, 320, HWSZ, 256);
    convert_split<<<NELEM/1024, 256>>>(p_tmp, p_tmph, p_tmpl);
    gemm_tcs<true ><<<dim3(5,4,56), 256>>>(p_tmph, p_tmpl, 320, HWSZ,
                                           p_DWh, p_DWl, 320, 0,
                                           p_xdct, 320, HWSZ, 320);

    // spectral attention branch -> g_xlow
    spec_attn_kernel<<<2560, 256>>>(spec_wq, spec_wk, spec_wv,
                                    spec_rs, spec_pw, spec_pb);

    // high-frequency path (combine emits split bf16 xout)
    pw1_gelu_kernel<<<NPIX/256, 256>>>(hf1_pw_w);
    dw_gelu_add_kernel<<<(NELEM+255)/256, 256>>>(hf1_dw_w);
    combine_kernel<<<NPIX/256, 256>>>(hf2_pw_w, coef_emb);

    // inverse 2D DCT
    gemm_tcs<false><<<dim3(5,4,56), 256>>>(p_DIHh, p_DIHl, 256, 0,
                                           p_xoh, p_xol, 320, HWSZ,
                                           p_tmp, 320, HWSZ, 256);
    convert_split<<<NELEM/1024, 256>>>(p_tmp, p_tmph, p_tmpl);
    gemm_tcs<true ><<<dim3(5,4,56), 256>>>(p_tmph, p_tmpl, 320, HWSZ,
                                           p_DIWh, p_DIWl, 320, 0,
                                           p_fd, 320, HWSZ, 320);

    // local attention branch -> g_loc (fused weights precomputed)
    loc_fuse_kernel<<<(12544+255)/256, 256>>>(loc_wq, loc_wkv, loc_pw);
    local_attn_kernel<<<2560, 256, LOCAL_SMEM>>>(x, loc_pos, loc_pb);

    // fusion -> NHWC output
    fusion_kernel<<<NPIX/256, 256>>>(fus_w, fus_b, out);
}